// round 1
// baseline (speedup 1.0000x reference)
#include <cuda_runtime.h>
#include <math.h>

// Shapes (fixed for this problem)
//   n = B*T = 8192 sequences, V = 25 tokens, D = 256, H = 8, HD = 32
//   qkv_w (256,768), proj_w (256,256), ffn_w1 (256,1024), ffn_w2 (1024,256)

#define V_TOK 25
#define DMODEL 256

__device__ __forceinline__ float warp_sum(float v) {
#pragma unroll
    for (int o = 16; o > 0; o >>= 1) v += __shfl_xor_sync(0xffffffffu, v, o);
    return v;
}
__device__ __forceinline__ float warp_max(float v) {
#pragma unroll
    for (int o = 16; o > 0; o >>= 1) v = fmaxf(v, __shfl_xor_sync(0xffffffffu, v, o));
    return v;
}

// C[32 x N] = A[32 x K] @ W[K x N] (+bias, opt gelu, opt accumulate into C)
// A, C in shared memory (rows 25..31 are don't-care padding), W/bias in global.
// 256 threads: ty = warp (8), tx = lane (32). Each thread: rows {ty,ty+8,ty+16,ty+24},
// cols {jb + 4*tx .. +3}. Weight tile 32(k) x 128(j) staged in s_w.
template<bool ACCUM, bool DOGELU>
__device__ __forceinline__ void gemm_seq(
    const float* A, int lda,
    const float* __restrict__ W, const float* __restrict__ bias,
    float* C, int ldc, int N, int K, float* s_w, int tid)
{
    const int ty = tid >> 5;
    const int tx = tid & 31;
    const int c4 = tx << 2;

    for (int jb = 0; jb < N; jb += 128) {
        float4 acc[4];
#pragma unroll
        for (int m = 0; m < 4; m++) { acc[m].x = acc[m].y = acc[m].z = acc[m].w = 0.0f; }

        for (int kb = 0; kb < K; kb += 32) {
            // stage W[kb:kb+32, jb:jb+128] -> s_w (32x128), 4 float4 per thread
#pragma unroll
            for (int u = 0; u < 4; u++) {
                int t = tid + u * 256;
                int r = t >> 5;
                int cc = (t & 31) << 2;
                *(float4*)&s_w[r * 128 + cc] =
                    *(const float4*)&W[(size_t)(kb + r) * N + jb + cc];
            }
            __syncthreads();
#pragma unroll
            for (int k = 0; k < 32; k++) {
                float4 w4 = *(const float4*)&s_w[k * 128 + c4];
                float a0 = A[(ty     ) * lda + kb + k];
                float a1 = A[(ty +  8) * lda + kb + k];
                float a2 = A[(ty + 16) * lda + kb + k];
                float a3 = A[(ty + 24) * lda + kb + k];
                acc[0].x += a0 * w4.x; acc[0].y += a0 * w4.y; acc[0].z += a0 * w4.z; acc[0].w += a0 * w4.w;
                acc[1].x += a1 * w4.x; acc[1].y += a1 * w4.y; acc[1].z += a1 * w4.z; acc[1].w += a1 * w4.w;
                acc[2].x += a2 * w4.x; acc[2].y += a2 * w4.y; acc[2].z += a2 * w4.z; acc[2].w += a2 * w4.w;
                acc[3].x += a3 * w4.x; acc[3].y += a3 * w4.y; acc[3].z += a3 * w4.z; acc[3].w += a3 * w4.w;
            }
            __syncthreads();
        }

        float4 b4 = *(const float4*)&bias[jb + c4];
#pragma unroll
        for (int m = 0; m < 4; m++) {
            int row = ty + 8 * m;
            float4 r4;
            r4.x = acc[m].x + b4.x;
            r4.y = acc[m].y + b4.y;
            r4.z = acc[m].z + b4.z;
            r4.w = acc[m].w + b4.w;
            if (DOGELU) {
                const float is2 = 0.70710678118654752f;
                r4.x = 0.5f * r4.x * (1.0f + erff(r4.x * is2));
                r4.y = 0.5f * r4.y * (1.0f + erff(r4.y * is2));
                r4.z = 0.5f * r4.z * (1.0f + erff(r4.z * is2));
                r4.w = 0.5f * r4.w * (1.0f + erff(r4.w * is2));
            }
            float4* cp = (float4*)&C[row * ldc + jb + c4];
            if (ACCUM) {
                float4 o = *cp;
                r4.x += o.x; r4.y += o.y; r4.z += o.z; r4.w += o.w;
            }
            *cp = r4;
        }
    }
}

// LayerNorm over D=256: one warp per row.
__device__ __forceinline__ void layer_norm_25(
    const float* in, float* outp,
    const float* __restrict__ g, const float* __restrict__ b,
    int warp, int lane)
{
    for (int r = warp; r < V_TOK; r += 8) {
        float xv[8];
        float s1 = 0.0f, s2 = 0.0f;
#pragma unroll
        for (int u = 0; u < 8; u++) {
            xv[u] = in[r * 256 + lane + 32 * u];
            s1 += xv[u];
            s2 += xv[u] * xv[u];
        }
        s1 = warp_sum(s1);
        s2 = warp_sum(s2);
        float mean = s1 * (1.0f / 256.0f);
        float var  = s2 * (1.0f / 256.0f) - mean * mean;
        float rs   = rsqrtf(var + 1e-5f);
#pragma unroll
        for (int u = 0; u < 8; u++) {
            int c = lane + 32 * u;
            outp[r * 256 + c] = (xv[u] - mean) * rs * g[c] + b[c];
        }
    }
}

__global__ void __launch_bounds__(256, 1)
spatial_attn_block_kernel(
    const float* __restrict__ x,
    const float* __restrict__ ln1_g, const float* __restrict__ ln1_b,
    const float* __restrict__ qkv_w, const float* __restrict__ qkv_b,
    const float* __restrict__ proj_w, const float* __restrict__ proj_b,
    const float* __restrict__ logit_scale,
    const float* __restrict__ ln2_g, const float* __restrict__ ln2_b,
    const float* __restrict__ ffn_w1, const float* __restrict__ ffn_b1,
    const float* __restrict__ ffn_w2, const float* __restrict__ ffn_b2,
    float* __restrict__ out)
{
    extern __shared__ float sm[];
    float* s_x   = sm;            // 32 x 256 residual
    float* s_y   = sm + 8192;     // 32 x 256 LN out (aliased as attn probs)
    float* s_big = sm + 16384;    // 32 x 1024: qkv (cols 0..767) + attn-out (768..1023); later FFN hidden
    float* s_w   = sm + 49152;    // 32 x 128 weight tile

    const int tid  = threadIdx.x;
    const int warp = tid >> 5;
    const int lane = tid & 31;
    const size_t base = (size_t)blockIdx.x * (V_TOK * DMODEL);

    // ---- load x (25x256) ----
    for (int t = tid; t < 1600; t += 256)
        *(float4*)&s_x[t * 4] = *(const float4*)&x[base + t * 4];
    __syncthreads();

    // ---- LN1 ----
    layer_norm_25(s_x, s_y, ln1_g, ln1_b, warp, lane);
    __syncthreads();

    // ---- QKV: s_big[:, 0:768] = LN1(x) @ qkv_w + qkv_b ----
    gemm_seq<false, false>(s_y, 256, qkv_w, qkv_b, s_big, 1024, 768, 256, s_w, tid);
    __syncthreads();

    // ---- attention: warp w handles head h = w ----
    {
        const int h = warp;
        const float LOG100 = 4.6051701859880914f;
        float scale = expf(fminf(logit_scale[h], LOG100));

        // normalize q (×scale) and k in place
        for (int i = 0; i < V_TOK; i++) {
            float qv = s_big[i * 1024 + h * 32 + lane];
            float sq = warp_sum(qv * qv);
            float qi = scale / fmaxf(sqrtf(sq), 1e-12f);
            s_big[i * 1024 + h * 32 + lane] = qv * qi;

            float kv = s_big[i * 1024 + 256 + h * 32 + lane];
            float sk = warp_sum(kv * kv);
            float ki = 1.0f / fmaxf(sqrtf(sk), 1e-12f);
            s_big[i * 1024 + 256 + h * 32 + lane] = kv * ki;
        }
        __syncwarp();

        // logits + softmax; attn probs into s_y[h*625 ...]
        float* s_attn = s_y + h * (V_TOK * V_TOK);
        const float inv_sqrt_d = 0.17677669529663687f; // 1/sqrt(32)
        for (int i = 0; i < V_TOK; i++) {
            float l = -INFINITY;
            if (lane < V_TOK) {
                float dot = 0.0f;
#pragma unroll
                for (int dd = 0; dd < 32; dd++) {
                    int d = (dd + lane) & 31; // lane rotation: conflict-free banks
                    dot += s_big[i * 1024 + h * 32 + d] *
                           s_big[lane * 1024 + 256 + h * 32 + d];
                }
                l = dot * inv_sqrt_d;
            }
            float mx = warp_max(l);
            float e = (lane < V_TOK) ? expf(l - mx) : 0.0f;
            float s = warp_sum(e);
            if (lane < V_TOK) s_attn[i * V_TOK + lane] = e / s;
        }
        __syncwarp();

        // out = attn @ v -> s_big[:, 768:1024] (concat-head layout)
        for (int i = 0; i < V_TOK; i++) {
            float o = 0.0f;
#pragma unroll 5
            for (int j = 0; j < V_TOK; j++)
                o += s_attn[i * V_TOK + j] * s_big[j * 1024 + 512 + h * 32 + lane];
            s_big[i * 1024 + 768 + h * 32 + lane] = o;
        }
    }
    __syncthreads();

    // ---- proj + residual: s_x += attn_out @ proj_w + proj_b ----
    gemm_seq<true, false>(s_big + 768, 1024, proj_w, proj_b, s_x, 256, 256, 256, s_w, tid);
    __syncthreads();

    // ---- LN2 ----
    layer_norm_25(s_x, s_y, ln2_g, ln2_b, warp, lane);
    __syncthreads();

    // ---- FFN1 + GELU: s_big = gelu(LN2 @ ffn_w1 + ffn_b1) ----
    gemm_seq<false, true>(s_y, 256, ffn_w1, ffn_b1, s_big, 1024, 1024, 256, s_w, tid);
    __syncthreads();

    // ---- FFN2 + residual: s_x += hidden @ ffn_w2 + ffn_b2 ----
    gemm_seq<true, false>(s_big, 1024, ffn_w2, ffn_b2, s_x, 256, 256, 1024, s_w, tid);
    __syncthreads();

    // ---- store ----
    for (int t = tid; t < 1600; t += 256)
        *(float4*)&out[base + t * 4] = *(float4*)&s_x[t * 4];
}

extern "C" void kernel_launch(void* const* d_in, const int* in_sizes, int n_in,
                              void* d_out, int out_size)
{
    const float* x           = (const float*)d_in[0];
    const float* ln1_g       = (const float*)d_in[1];
    const float* ln1_b       = (const float*)d_in[2];
    const float* qkv_w       = (const float*)d_in[3];
    const float* qkv_b       = (const float*)d_in[4];
    const float* proj_w      = (const float*)d_in[5];
    const float* proj_b      = (const float*)d_in[6];
    const float* logit_scale = (const float*)d_in[7];
    const float* ln2_g       = (const float*)d_in[8];
    const float* ln2_b       = (const float*)d_in[9];
    const float* ffn_w1      = (const float*)d_in[10];
    const float* ffn_b1      = (const float*)d_in[11];
    const float* ffn_w2      = (const float*)d_in[12];
    const float* ffn_b2      = (const float*)d_in[13];
    float* out = (float*)d_out;

    int n_seq = out_size / (V_TOK * DMODEL);   // 8192
    int smem_bytes = 53248 * (int)sizeof(float);  // 212992

    cudaFuncSetAttribute(spatial_attn_block_kernel,
                         cudaFuncAttributeMaxDynamicSharedMemorySize, smem_bytes);

    spatial_attn_block_kernel<<<n_seq, 256, smem_bytes>>>(
        x, ln1_g, ln1_b, qkv_w, qkv_b, proj_w, proj_b, logit_scale,
        ln2_g, ln2_b, ffn_w1, ffn_b1, ffn_w2, ffn_b2, out);
}

// round 4
// speedup vs baseline: 3.6694x; 3.6694x over previous
#include <cuda_runtime.h>
#include <cuda_bf16.h>
#include <math.h>
#include <stdint.h>

// Problem dims: n = 8192 sequences, V=25 tokens, D=256, H=8, HD=32
#define NSEQ  8192
#define M_TOT 204800        // 8192*25, divisible by 128 -> 1600 M-tiles

// ---------------- device scratch (allocation-free: __device__ globals) -------
__device__ __nv_bfloat16 g_ahi[(size_t)M_TOT * 256];
__device__ __nv_bfloat16 g_alo[(size_t)M_TOT * 256];
__device__ float         g_qkv[(size_t)M_TOT * 768];
__device__ __nv_bfloat16 g_hhi[(size_t)M_TOT * 1024];
__device__ __nv_bfloat16 g_hlo[(size_t)M_TOT * 1024];
// transposed split weights: [qkv 768x256 | proj 256x256 | ffn1 1024x256 | ffn2 256x1024]
#define WOFF_QKV  0
#define WOFF_PROJ 196608
#define WOFF_F1   262144
#define WOFF_F2   524288
__device__ __nv_bfloat16 g_whi[786432];
__device__ __nv_bfloat16 g_wlo[786432];

// ---------------- PTX helpers ------------------------------------------------
__device__ __forceinline__ uint32_t smem_u32(const void* p) {
    uint32_t a;
    asm("{ .reg .u64 t; cvta.to.shared.u64 t, %1; cvt.u32.u64 %0, t; }" : "=r"(a) : "l"(p));
    return a;
}
#define CP_COMMIT() asm volatile("cp.async.commit_group;" ::: "memory")
#define CP_WAIT1()  asm volatile("cp.async.wait_group 1;" ::: "memory")
__device__ __forceinline__ void cpa16(uint32_t dst, const void* src) {
    asm volatile("cp.async.cg.shared.global [%0], [%1], 16;" :: "r"(dst), "l"(src));
}
__device__ __forceinline__ void ldm_x4(uint32_t& r0, uint32_t& r1, uint32_t& r2, uint32_t& r3, uint32_t addr) {
    asm volatile("ldmatrix.sync.aligned.m8n8.x4.shared.b16 {%0,%1,%2,%3}, [%4];"
                 : "=r"(r0), "=r"(r1), "=r"(r2), "=r"(r3) : "r"(addr));
}
__device__ __forceinline__ void mma_bf16(float* d, const uint32_t* a, uint32_t b0, uint32_t b1) {
    asm volatile("mma.sync.aligned.m16n8k16.row.col.f32.bf16.bf16.f32 "
                 "{%0,%1,%2,%3},{%4,%5,%6,%7},{%8,%9},{%0,%1,%2,%3};"
                 : "+f"(d[0]), "+f"(d[1]), "+f"(d[2]), "+f"(d[3])
                 : "r"(a[0]), "r"(a[1]), "r"(a[2]), "r"(a[3]), "r"(b0), "r"(b1));
}

__device__ __forceinline__ float warp_sum(float v) {
#pragma unroll
    for (int o = 16; o > 0; o >>= 1) v += __shfl_xor_sync(0xffffffffu, v, o);
    return v;
}
__device__ __forceinline__ float warp_max(float v) {
#pragma unroll
    for (int o = 16; o > 0; o >>= 1) v = fmaxf(v, __shfl_xor_sync(0xffffffffu, v, o));
    return v;
}
__device__ __forceinline__ void split2(float v, __nv_bfloat16& hi, __nv_bfloat16& lo) {
    hi = __float2bfloat16(v);
    lo = __float2bfloat16(v - __bfloat162float(hi));
}

// ---------------- weight prep: transpose + bf16 split ------------------------
__global__ void prep_w_kernel(const float* __restrict__ qkvw, const float* __restrict__ projw,
                              const float* __restrict__ f1w, const float* __restrict__ f2w) {
    int idx = blockIdx.x * 256 + threadIdx.x;
    if (idx >= 786432) return;
    const float* src; int K, N, local;
    if (idx < WOFF_PROJ)    { src = qkvw;  K = 256;  N = 768;  local = idx; }
    else if (idx < WOFF_F1) { src = projw; K = 256;  N = 256;  local = idx - WOFF_PROJ; }
    else if (idx < WOFF_F2) { src = f1w;   K = 256;  N = 1024; local = idx - WOFF_F1; }
    else                    { src = f2w;   K = 1024; N = 256;  local = idx - WOFF_F2; }
    int n = local / K, k = local % K;
    float v = src[(size_t)k * N + n];
    __nv_bfloat16 h, l; split2(v, h, l);
    g_whi[idx] = h; g_wlo[idx] = l;
}

// ---------------- LayerNorm + split: one warp per row ------------------------
__global__ void __launch_bounds__(256) ln_split_kernel(
    const float* __restrict__ in, const float* __restrict__ g, const float* __restrict__ b) {
    int row = blockIdx.x * 8 + (threadIdx.x >> 5);
    int lane = threadIdx.x & 31;
    const float* rp = in + (size_t)row * 256;
    float xv[8], s1 = 0.f, s2 = 0.f;
#pragma unroll
    for (int u = 0; u < 8; u++) {
        xv[u] = rp[lane + 32 * u];
        s1 += xv[u]; s2 += xv[u] * xv[u];
    }
    s1 = warp_sum(s1); s2 = warp_sum(s2);
    float mean = s1 * (1.f / 256.f);
    float var = s2 * (1.f / 256.f) - mean * mean;
    float rs = rsqrtf(var + 1e-5f);
    size_t ob = (size_t)row * 256;
#pragma unroll
    for (int u = 0; u < 8; u++) {
        int c = lane + 32 * u;
        float y = (xv[u] - mean) * rs * g[c] + b[c];
        __nv_bfloat16 h, l; split2(y, h, l);
        g_ahi[ob + c] = h; g_alo[ob + c] = l;
    }
}

// ---------------- HMMA GEMM: C[M_TOT x Ntot] = A @ Wt^T (3-term bf16 split)
// A: [M_TOT x K] row-major (hi/lo); Wt: [Ntot x K] K-contiguous (hi/lo).
// CTA 128x128, warp tile 64x32 (2x4 warps), K-tile 64, double-buffered cp.async.
#define ST_SZ   32768          // per stage: A 16KB + B 16KB
#define GEMM_SMEM (2 * ST_SZ)  // 64KB

__device__ __forceinline__ void load_tile(uint32_t stage_base,
    const __nv_bfloat16* __restrict__ A, const __nv_bfloat16* __restrict__ B,
    int K, int kk, int m0, int n0, int tid)
{
    uint32_t aB = stage_base;
    uint32_t bB = stage_base + 16384;
#pragma unroll
    for (int i = 0; i < 4; i++) {
        int idx = tid + i * 256;
        int r = idx >> 3, c = idx & 7;                 // row 0..127, 16B chunk 0..7
        uint32_t off = (uint32_t)(r * 128 + c * 16);
        uint32_t sw = off ^ ((uint32_t)(r & 7) << 4);  // SW128
        cpa16(aB + sw, A + (size_t)(m0 + r) * K + kk + c * 8);
    }
#pragma unroll
    for (int i = 0; i < 4; i++) {
        int idx = tid + i * 256;
        int r = idx >> 3, c = idx & 7;
        uint32_t off = (uint32_t)(r * 128 + c * 16);
        uint32_t sw = off ^ ((uint32_t)(r & 7) << 4);
        cpa16(bB + sw, B + (size_t)(n0 + r) * K + kk + c * 8);
    }
}

template<bool GELU, bool SPLIT, bool RESID>
__global__ void __launch_bounds__(256, 2) gemm_mma(
    const __nv_bfloat16* __restrict__ Ahi, const __nv_bfloat16* __restrict__ Alo,
    int K, int woff, const float* __restrict__ bias, int Ntot,
    float* __restrict__ outF, __nv_bfloat16* __restrict__ outHi, __nv_bfloat16* __restrict__ outLo,
    const float* __restrict__ resid)
{
    extern __shared__ char smem[];
    uint32_t sb = smem_u32(smem);
    const int tid = threadIdx.x, wid = tid >> 5, lane = tid & 31;
    const int wm = wid & 1, wn = wid >> 1;
    const int m0 = blockIdx.y * 128, n0 = blockIdx.x * 128;
    const int KT = K >> 6;
    const int NT = 3 * KT;
    const __nv_bfloat16* Wh = g_whi + woff;
    const __nv_bfloat16* Wl = g_wlo + woff;

    float acc[4][4][4];
#pragma unroll
    for (int i = 0; i < 4; i++)
#pragma unroll
        for (int j = 0; j < 4; j++)
#pragma unroll
            for (int kq = 0; kq < 4; kq++) acc[i][j][kq] = 0.f;

    // term/tile selector
    auto pick = [&](int kt, const __nv_bfloat16*& a, const __nv_bfloat16*& b, int& kk) {
        int t = kt / KT;
        kk = (kt % KT) * 64;
        a = (t < 2) ? Ahi : Alo;
        b = (t == 1) ? Wl : Wh;
    };

    { const __nv_bfloat16 *a, *b; int kk;
      pick(0, a, b, kk); load_tile(sb,         a, b, K, kk, m0, n0, tid); CP_COMMIT();
      pick(1, a, b, kk); load_tile(sb + ST_SZ, a, b, K, kk, m0, n0, tid); CP_COMMIT(); }

    // per-lane ldmatrix geometry
    const int grp = lane >> 3, lr = lane & 7;
    const int a_row_b = wm * 64 + (grp & 1) * 8 + lr;   // + mf*16
    const int a_kb    = (grp >> 1) * 16;                // bytes
    const int b_row_b = wn * 32 + (grp >> 1) * 8 + lr;  // + np*16
    const int b_kb    = (grp & 1) * 16;                 // bytes

    for (int kt = 0; kt < NT; kt++) {
        const int s = kt & 1;
        CP_WAIT1();
        __syncthreads();

        const uint32_t aBase = sb + s * ST_SZ;
        const uint32_t bBase = aBase + 16384;
#pragma unroll
        for (int ks = 0; ks < 4; ks++) {
            const int kb = ks * 32;  // bytes into the 128B row
            uint32_t af[4][4];
#pragma unroll
            for (int mf = 0; mf < 4; mf++) {
                int row = a_row_b + mf * 16;
                uint32_t off = (uint32_t)(row * 128 + kb + a_kb);
                uint32_t addr = aBase + (off ^ ((uint32_t)(row & 7) << 4));
                ldm_x4(af[mf][0], af[mf][1], af[mf][2], af[mf][3], addr);
            }
            uint32_t bf[2][4];
#pragma unroll
            for (int np = 0; np < 2; np++) {
                int row = b_row_b + np * 16;
                uint32_t off = (uint32_t)(row * 128 + kb + b_kb);
                uint32_t addr = bBase + (off ^ ((uint32_t)(row & 7) << 4));
                ldm_x4(bf[np][0], bf[np][1], bf[np][2], bf[np][3], addr);
            }
#pragma unroll
            for (int mf = 0; mf < 4; mf++)
#pragma unroll
                for (int nf = 0; nf < 4; nf++)
                    mma_bf16(acc[mf][nf], af[mf], bf[nf >> 1][(nf & 1) * 2], bf[nf >> 1][(nf & 1) * 2 + 1]);
        }
        __syncthreads();
        if (kt + 2 < NT) {
            const __nv_bfloat16 *a, *b; int kk;
            pick(kt + 2, a, b, kk);
            load_tile(sb + s * ST_SZ, a, b, K, kk, m0, n0, tid);
        }
        CP_COMMIT();
    }

    // -------- epilogue --------
    const int qr = lane >> 2;            // 0..7
    const int qc = (lane & 3) * 2;       // 0,2,4,6
#pragma unroll
    for (int mf = 0; mf < 4; mf++) {
#pragma unroll
        for (int nf = 0; nf < 4; nf++) {
            int C = n0 + wn * 32 + nf * 8 + qc;
            float b0 = __ldg(&bias[C]), b1 = __ldg(&bias[C + 1]);
#pragma unroll
            for (int half = 0; half < 2; half++) {
                int R = m0 + wm * 64 + mf * 16 + qr + half * 8;
                float v0 = acc[mf][nf][half * 2 + 0] + b0;
                float v1 = acc[mf][nf][half * 2 + 1] + b1;
                if (GELU) {
                    const float is2 = 0.70710678118654752f;
                    v0 = 0.5f * v0 * (1.0f + erff(v0 * is2));
                    v1 = 0.5f * v1 * (1.0f + erff(v1 * is2));
                }
                size_t gidx = (size_t)R * Ntot + C;
                if (RESID) {
                    float2 rv = *(const float2*)&resid[gidx];
                    v0 += rv.x; v1 += rv.y;
                }
                if (SPLIT) {
                    __nv_bfloat16 h0, l0, h1, l1;
                    split2(v0, h0, l0); split2(v1, h1, l1);
                    *(__nv_bfloat162*)&outHi[gidx] = __nv_bfloat162(h0, h1);
                    *(__nv_bfloat162*)&outLo[gidx] = __nv_bfloat162(l0, l1);
                } else {
                    *(float2*)&outF[gidx] = make_float2(v0, v1);
                }
            }
        }
    }
}

// ---------------- attention: one CTA per sequence, warp = head --------------
#define ATTN_SMEM ((19200 + 8 * 625) * 4)
__global__ void __launch_bounds__(256, 1) attn_kernel(const float* __restrict__ logit_scale) {
    extern __shared__ float sq[];
    float* s_attn = sq + 19200;
    const int tid = threadIdx.x, h = tid >> 5, lane = tid & 31;
    const size_t n = blockIdx.x;
    const float* qkv = g_qkv + n * 19200;
    for (int i = tid; i < 4800; i += 256)
        ((float4*)sq)[i] = ((const float4*)qkv)[i];
    __syncthreads();

    const float LOG100 = 4.6051701859880914f;
    float scale = expf(fminf(logit_scale[h], LOG100));

    for (int i = 0; i < 25; i++) {
        float qv = sq[i * 768 + h * 32 + lane];
        float sqs = warp_sum(qv * qv);
        sq[i * 768 + h * 32 + lane] = qv * (scale / fmaxf(sqrtf(sqs), 1e-12f));
        float kv = sq[i * 768 + 256 + h * 32 + lane];
        float sks = warp_sum(kv * kv);
        sq[i * 768 + 256 + h * 32 + lane] = kv * (1.0f / fmaxf(sqrtf(sks), 1e-12f));
    }
    __syncwarp();

    float* sa = s_attn + h * 625;
    const float inv_sqrt_d = 0.17677669529663687f;
    for (int i = 0; i < 25; i++) {
        float l = -INFINITY;
        if (lane < 25) {
            float dot = 0.f;
#pragma unroll
            for (int dd = 0; dd < 32; dd++) {
                int d = (dd + lane) & 31;
                dot += sq[i * 768 + h * 32 + d] * sq[lane * 768 + 256 + h * 32 + d];
            }
            l = dot * inv_sqrt_d;
        }
        float mx = warp_max(l);
        float e = (lane < 25) ? expf(l - mx) : 0.f;
        float s = warp_sum(e);
        if (lane < 25) sa[i * 25 + lane] = e / s;
    }
    __syncwarp();

    for (int i = 0; i < 25; i++) {
        float o = 0.f;
#pragma unroll 5
        for (int j = 0; j < 25; j++)
            o += sa[i * 25 + j] * sq[j * 768 + 512 + h * 32 + lane];
        __nv_bfloat16 hh, ll; split2(o, hh, ll);
        size_t gidx = (n * 25 + i) * 256 + h * 32 + lane;
        g_ahi[gidx] = hh; g_alo[gidx] = ll;
    }
}

// ---------------- launch -----------------------------------------------------
extern "C" void kernel_launch(void* const* d_in, const int* in_sizes, int n_in,
                              void* d_out, int out_size)
{
    const float* x           = (const float*)d_in[0];
    const float* ln1_g       = (const float*)d_in[1];
    const float* ln1_b       = (const float*)d_in[2];
    const float* qkv_w       = (const float*)d_in[3];
    const float* qkv_b       = (const float*)d_in[4];
    const float* proj_w      = (const float*)d_in[5];
    const float* proj_b      = (const float*)d_in[6];
    const float* logit_scale = (const float*)d_in[7];
    const float* ln2_g       = (const float*)d_in[8];
    const float* ln2_b       = (const float*)d_in[9];
    const float* ffn_w1      = (const float*)d_in[10];
    const float* ffn_b1      = (const float*)d_in[11];
    const float* ffn_w2      = (const float*)d_in[12];
    const float* ffn_b2      = (const float*)d_in[13];
    float* out = (float*)d_out;

    cudaFuncSetAttribute(gemm_mma<false,false,false>, cudaFuncAttributeMaxDynamicSharedMemorySize, GEMM_SMEM);
    cudaFuncSetAttribute(gemm_mma<false,false,true >, cudaFuncAttributeMaxDynamicSharedMemorySize, GEMM_SMEM);
    cudaFuncSetAttribute(gemm_mma<true ,true ,false>, cudaFuncAttributeMaxDynamicSharedMemorySize, GEMM_SMEM);
    cudaFuncSetAttribute(attn_kernel, cudaFuncAttributeMaxDynamicSharedMemorySize, ATTN_SMEM);

    __nv_bfloat16 *ahi, *alo, *hhi, *hlo;
    float* qkvp;
    cudaGetSymbolAddress((void**)&ahi, g_ahi);
    cudaGetSymbolAddress((void**)&alo, g_alo);
    cudaGetSymbolAddress((void**)&hhi, g_hhi);
    cudaGetSymbolAddress((void**)&hlo, g_hlo);
    cudaGetSymbolAddress((void**)&qkvp, g_qkv);

    // 1) weight transpose + bf16 split
    prep_w_kernel<<<3072, 256>>>(qkv_w, proj_w, ffn_w1, ffn_w2);
    // 2) LN1 -> split activations
    ln_split_kernel<<<M_TOT / 8, 256>>>(x, ln1_g, ln1_b);
    // 3) QKV GEMM -> g_qkv (fp32)
    gemm_mma<false,false,false><<<dim3(6, 1600), 256, GEMM_SMEM>>>(
        ahi, alo, 256, WOFF_QKV, qkv_b, 768, qkvp, nullptr, nullptr, nullptr);
    // 4) attention -> split attn-out into g_ahi/g_alo
    attn_kernel<<<NSEQ, 256, ATTN_SMEM>>>(logit_scale);
    // 5) proj GEMM + residual(x) -> d_out (fp32)
    gemm_mma<false,false,true><<<dim3(2, 1600), 256, GEMM_SMEM>>>(
        ahi, alo, 256, WOFF_PROJ, proj_b, 256, out, nullptr, nullptr, x);
    // 6) LN2 -> split activations
    ln_split_kernel<<<M_TOT / 8, 256>>>(out, ln2_g, ln2_b);
    // 7) FFN1 GEMM + GELU -> split hidden
    gemm_mma<true,true,false><<<dim3(8, 1600), 256, GEMM_SMEM>>>(
        ahi, alo, 256, WOFF_F1, ffn_b1, 1024, nullptr, hhi, hlo, nullptr);
    // 8) FFN2 GEMM + residual -> d_out (final)
    gemm_mma<false,false,true><<<dim3(2, 1600), 256, GEMM_SMEM>>>(
        hhi, hlo, 1024, WOFF_F2, ffn_b2, 256, out, nullptr, nullptr, out);
}

// round 7
// speedup vs baseline: 6.2119x; 1.6929x over previous
#include <cuda_runtime.h>
#include <cuda_fp16.h>
#include <math.h>
#include <stdint.h>

// Problem dims: n = 8192 sequences, V=25 tokens, D=256, H=8, HD=32
#define NSEQ  8192
#define M_TOT 204800        // 8192*25, divisible by 128 -> 1600 M-tiles

// ---------------- device scratch (allocation-free: __device__ globals) -------
__device__ __half g_a[(size_t)M_TOT * 256];     // activations (fp16)
__device__ __half g_qkv[(size_t)M_TOT * 768];   // qkv out (fp16)
__device__ __half g_h[(size_t)M_TOT * 1024];    // ffn hidden (fp16)
// transposed weights: [qkv 768x256 | proj 256x256 | ffn1 1024x256 | ffn2 256x1024]
#define WOFF_QKV  0
#define WOFF_PROJ 196608
#define WOFF_F1   262144
#define WOFF_F2   524288
__device__ __half g_w[786432];

// ---------------- PTX helpers ------------------------------------------------
__device__ __forceinline__ uint32_t smem_u32(const void* p) {
    uint32_t a;
    asm("{ .reg .u64 t; cvta.to.shared.u64 t, %1; cvt.u32.u64 %0, t; }" : "=r"(a) : "l"(p));
    return a;
}
#define CP_COMMIT() asm volatile("cp.async.commit_group;" ::: "memory")
#define CP_WAIT1()  asm volatile("cp.async.wait_group 1;" ::: "memory")
__device__ __forceinline__ void cpa16(uint32_t dst, const void* src) {
    asm volatile("cp.async.cg.shared.global [%0], [%1], 16;" :: "r"(dst), "l"(src));
}
__device__ __forceinline__ void ldm_x4(uint32_t& r0, uint32_t& r1, uint32_t& r2, uint32_t& r3, uint32_t addr) {
    asm volatile("ldmatrix.sync.aligned.m8n8.x4.shared.b16 {%0,%1,%2,%3}, [%4];"
                 : "=r"(r0), "=r"(r1), "=r"(r2), "=r"(r3) : "r"(addr));
}
__device__ __forceinline__ void mma_fp16(float* d, const uint32_t* a, uint32_t b0, uint32_t b1) {
    asm volatile("mma.sync.aligned.m16n8k16.row.col.f32.f16.f16.f32 "
                 "{%0,%1,%2,%3},{%4,%5,%6,%7},{%8,%9},{%0,%1,%2,%3};"
                 : "+f"(d[0]), "+f"(d[1]), "+f"(d[2]), "+f"(d[3])
                 : "r"(a[0]), "r"(a[1]), "r"(a[2]), "r"(a[3]), "r"(b0), "r"(b1));
}

__device__ __forceinline__ float warp_sum(float v) {
#pragma unroll
    for (int o = 16; o > 0; o >>= 1) v += __shfl_xor_sync(0xffffffffu, v, o);
    return v;
}
__device__ __forceinline__ float warp_max(float v) {
#pragma unroll
    for (int o = 16; o > 0; o >>= 1) v = fmaxf(v, __shfl_xor_sync(0xffffffffu, v, o));
    return v;
}

// ---------------- weight prep: transpose to [N x K] fp16 ---------------------
__global__ void prep_w_kernel(const float* __restrict__ qkvw, const float* __restrict__ projw,
                              const float* __restrict__ f1w, const float* __restrict__ f2w) {
    int idx = blockIdx.x * 256 + threadIdx.x;
    if (idx >= 786432) return;
    const float* src; int K, N, local;
    if (idx < WOFF_PROJ)    { src = qkvw;  K = 256;  N = 768;  local = idx; }
    else if (idx < WOFF_F1) { src = projw; K = 256;  N = 256;  local = idx - WOFF_PROJ; }
    else if (idx < WOFF_F2) { src = f1w;   K = 256;  N = 1024; local = idx - WOFF_F1; }
    else                    { src = f2w;   K = 1024; N = 256;  local = idx - WOFF_F2; }
    int n = local / K, k = local % K;
    g_w[idx] = __float2half_rn(src[(size_t)k * N + n]);
}

// ---------------- LayerNorm -> fp16: one warp per row ------------------------
__global__ void __launch_bounds__(256) ln_h_kernel(
    const float* __restrict__ in, const float* __restrict__ g, const float* __restrict__ b) {
    int row = blockIdx.x * 8 + (threadIdx.x >> 5);
    int lane = threadIdx.x & 31;
    const float* rp = in + (size_t)row * 256;
    float xv[8], s1 = 0.f, s2 = 0.f;
#pragma unroll
    for (int u = 0; u < 8; u++) {
        xv[u] = rp[lane + 32 * u];
        s1 += xv[u]; s2 += xv[u] * xv[u];
    }
    s1 = warp_sum(s1); s2 = warp_sum(s2);
    float mean = s1 * (1.f / 256.f);
    float var = s2 * (1.f / 256.f) - mean * mean;
    float rs = rsqrtf(var + 1e-5f);
    size_t ob = (size_t)row * 256;
#pragma unroll
    for (int u = 0; u < 8; u++) {
        int c = lane + 32 * u;
        g_a[ob + c] = __float2half_rn((xv[u] - mean) * rs * g[c] + b[c]);
    }
}

// ---------------- HMMA fp16 GEMM: C[M_TOT x Ntot] = A @ Wt^T -----------------
// A: [M_TOT x K] row-major fp16; Wt: [Ntot x K] K-contiguous fp16.
// CTA 128x128, warp tile 64x32 (2x4 warps), K-tile 64, double-buffered cp.async.
#define ST_SZ   32768          // per stage: A 16KB + B 16KB
#define GEMM_SMEM (2 * ST_SZ)  // 64KB

__device__ __forceinline__ void load_tile(uint32_t stage_base,
    const __half* __restrict__ A, const __half* __restrict__ B,
    int K, int kk, int m0, int n0, int tid)
{
    uint32_t aB = stage_base;
    uint32_t bB = stage_base + 16384;
#pragma unroll
    for (int i = 0; i < 4; i++) {
        int idx = tid + i * 256;
        int r = idx >> 3, c = idx & 7;                 // row 0..127, 16B chunk 0..7
        uint32_t off = (uint32_t)(r * 128 + c * 16);
        uint32_t sw = off ^ ((uint32_t)(r & 7) << 4);  // SW128
        cpa16(aB + sw, A + (size_t)(m0 + r) * K + kk + c * 8);
    }
#pragma unroll
    for (int i = 0; i < 4; i++) {
        int idx = tid + i * 256;
        int r = idx >> 3, c = idx & 7;
        uint32_t off = (uint32_t)(r * 128 + c * 16);
        uint32_t sw = off ^ ((uint32_t)(r & 7) << 4);
        cpa16(bB + sw, B + (size_t)(n0 + r) * K + kk + c * 8);
    }
}

template<bool GELU, bool HALFOUT, bool RESID>
__global__ void __launch_bounds__(256, 2) gemm_mma(
    const __half* __restrict__ A, int K, int woff,
    const float* __restrict__ bias, int Ntot,
    float* __restrict__ outF, __half* __restrict__ outH,
    const float* __restrict__ resid)
{
    extern __shared__ char smem[];
    uint32_t sb = smem_u32(smem);
    const int tid = threadIdx.x, wid = tid >> 5, lane = tid & 31;
    const int wm = wid & 1, wn = wid >> 1;
    const int m0 = blockIdx.y * 128, n0 = blockIdx.x * 128;
    const int NT = K >> 6;
    const __half* W = g_w + woff;

    float acc[4][4][4];
#pragma unroll
    for (int i = 0; i < 4; i++)
#pragma unroll
        for (int j = 0; j < 4; j++)
#pragma unroll
            for (int kq = 0; kq < 4; kq++) acc[i][j][kq] = 0.f;

    load_tile(sb,         A, W, K, 0,  m0, n0, tid); CP_COMMIT();
    load_tile(sb + ST_SZ, A, W, K, 64, m0, n0, tid); CP_COMMIT();

    // per-lane ldmatrix geometry
    const int grp = lane >> 3, lr = lane & 7;
    const int a_row_b = wm * 64 + (grp & 1) * 8 + lr;   // + mf*16
    const int a_kb    = (grp >> 1) * 16;                // bytes
    const int b_row_b = wn * 32 + (grp >> 1) * 8 + lr;  // + np*16
    const int b_kb    = (grp & 1) * 16;                 // bytes

    for (int kt = 0; kt < NT; kt++) {
        const int s = kt & 1;
        CP_WAIT1();
        __syncthreads();

        const uint32_t aBase = sb + s * ST_SZ;
        const uint32_t bBase = aBase + 16384;
#pragma unroll
        for (int ks = 0; ks < 4; ks++) {
            const int kb = ks * 32;  // bytes into the 128B row
            uint32_t af[4][4];
#pragma unroll
            for (int mf = 0; mf < 4; mf++) {
                int row = a_row_b + mf * 16;
                uint32_t off = (uint32_t)(row * 128 + kb + a_kb);
                uint32_t addr = aBase + (off ^ ((uint32_t)(row & 7) << 4));
                ldm_x4(af[mf][0], af[mf][1], af[mf][2], af[mf][3], addr);
            }
            uint32_t bf[2][4];
#pragma unroll
            for (int np = 0; np < 2; np++) {
                int row = b_row_b + np * 16;
                uint32_t off = (uint32_t)(row * 128 + kb + b_kb);
                uint32_t addr = bBase + (off ^ ((uint32_t)(row & 7) << 4));
                ldm_x4(bf[np][0], bf[np][1], bf[np][2], bf[np][3], addr);
            }
#pragma unroll
            for (int mf = 0; mf < 4; mf++)
#pragma unroll
                for (int nf = 0; nf < 4; nf++)
                    mma_fp16(acc[mf][nf], af[mf], bf[nf >> 1][(nf & 1) * 2], bf[nf >> 1][(nf & 1) * 2 + 1]);
        }
        __syncthreads();
        if (kt + 2 < NT)
            load_tile(sb + s * ST_SZ, A, W, K, (kt + 2) * 64, m0, n0, tid);
        CP_COMMIT();
    }

    // -------- epilogue --------
    const int qr = lane >> 2;            // 0..7
    const int qc = (lane & 3) * 2;       // 0,2,4,6
#pragma unroll
    for (int mf = 0; mf < 4; mf++) {
#pragma unroll
        for (int nf = 0; nf < 4; nf++) {
            int C = n0 + wn * 32 + nf * 8 + qc;
            float b0 = __ldg(&bias[C]), b1 = __ldg(&bias[C + 1]);
#pragma unroll
            for (int half_ = 0; half_ < 2; half_++) {
                int R = m0 + wm * 64 + mf * 16 + qr + half_ * 8;
                float v0 = acc[mf][nf][half_ * 2 + 0] + b0;
                float v1 = acc[mf][nf][half_ * 2 + 1] + b1;
                if (GELU) {
                    const float is2 = 0.70710678118654752f;
                    v0 = 0.5f * v0 * (1.0f + erff(v0 * is2));
                    v1 = 0.5f * v1 * (1.0f + erff(v1 * is2));
                }
                size_t gidx = (size_t)R * Ntot + C;
                if (RESID) {
                    float2 rv = *(const float2*)&resid[gidx];
                    v0 += rv.x; v1 += rv.y;
                }
                if (HALFOUT) {
                    *(__half2*)&outH[gidx] = __floats2half2_rn(v0, v1);
                } else {
                    *(float2*)&outF[gidx] = make_float2(v0, v1);
                }
            }
        }
    }
}

// ---------------- attention: one CTA per sequence, warp = head --------------
#define ATTN_SMEM ((19200 + 8 * 625) * 4)
__global__ void __launch_bounds__(256, 1) attn_kernel(const float* __restrict__ logit_scale) {
    extern __shared__ float sq[];
    float* s_attn = sq + 19200;
    const int tid = threadIdx.x, h = tid >> 5, lane = tid & 31;
    const size_t n = blockIdx.x;
    const __half2* qkv = (const __half2*)(g_qkv + n * 19200);
    for (int i = tid; i < 9600; i += 256) {
        float2 f = __half22float2(qkv[i]);
        sq[2 * i] = f.x; sq[2 * i + 1] = f.y;
    }
    __syncthreads();

    const float LOG100 = 4.6051701859880914f;
    float scale = expf(fminf(logit_scale[h], LOG100));

    for (int i = 0; i < 25; i++) {
        float qv = sq[i * 768 + h * 32 + lane];
        float sqs = warp_sum(qv * qv);
        sq[i * 768 + h * 32 + lane] = qv * (scale / fmaxf(sqrtf(sqs), 1e-12f));
        float kv = sq[i * 768 + 256 + h * 32 + lane];
        float sks = warp_sum(kv * kv);
        sq[i * 768 + 256 + h * 32 + lane] = kv * (1.0f / fmaxf(sqrtf(sks), 1e-12f));
    }
    __syncwarp();

    float* sa = s_attn + h * 625;
    const float inv_sqrt_d = 0.17677669529663687f;
    for (int i = 0; i < 25; i++) {
        float l = -INFINITY;
        if (lane < 25) {
            float dot = 0.f;
#pragma unroll
            for (int dd = 0; dd < 32; dd++) {
                int d = (dd + lane) & 31;
                dot += sq[i * 768 + h * 32 + d] * sq[lane * 768 + 256 + h * 32 + d];
            }
            l = dot * inv_sqrt_d;
        }
        float mx = warp_max(l);
        float e = (lane < 25) ? expf(l - mx) : 0.f;
        float s = warp_sum(e);
        if (lane < 25) sa[i * 25 + lane] = e / s;
    }
    __syncwarp();

    for (int i = 0; i < 25; i++) {
        float o = 0.f;
#pragma unroll 5
        for (int j = 0; j < 25; j++)
            o += sa[i * 25 + j] * sq[j * 768 + 512 + h * 32 + lane];
        g_a[(n * 25 + i) * 256 + h * 32 + lane] = __float2half_rn(o);
    }
}

// ---------------- launch -----------------------------------------------------
extern "C" void kernel_launch(void* const* d_in, const int* in_sizes, int n_in,
                              void* d_out, int out_size)
{
    const float* x           = (const float*)d_in[0];
    const float* ln1_g       = (const float*)d_in[1];
    const float* ln1_b       = (const float*)d_in[2];
    const float* qkv_w       = (const float*)d_in[3];
    const float* qkv_b       = (const float*)d_in[4];
    const float* proj_w      = (const float*)d_in[5];
    const float* proj_b      = (const float*)d_in[6];
    const float* logit_scale = (const float*)d_in[7];
    const float* ln2_g       = (const float*)d_in[8];
    const float* ln2_b       = (const float*)d_in[9];
    const float* ffn_w1      = (const float*)d_in[10];
    const float* ffn_b1      = (const float*)d_in[11];
    const float* ffn_w2      = (const float*)d_in[12];
    const float* ffn_b2      = (const float*)d_in[13];
    float* out = (float*)d_out;

    cudaFuncSetAttribute(gemm_mma<false,true ,false>, cudaFuncAttributeMaxDynamicSharedMemorySize, GEMM_SMEM);
    cudaFuncSetAttribute(gemm_mma<false,false,true >, cudaFuncAttributeMaxDynamicSharedMemorySize, GEMM_SMEM);
    cudaFuncSetAttribute(gemm_mma<true ,true ,false>, cudaFuncAttributeMaxDynamicSharedMemorySize, GEMM_SMEM);
    cudaFuncSetAttribute(attn_kernel, cudaFuncAttributeMaxDynamicSharedMemorySize, ATTN_SMEM);

    __half *ap, *qkvp, *hp;
    cudaGetSymbolAddress((void**)&ap,   g_a);
    cudaGetSymbolAddress((void**)&qkvp, g_qkv);
    cudaGetSymbolAddress((void**)&hp,   g_h);

    // 1) weight transpose -> fp16
    prep_w_kernel<<<3072, 256>>>(qkv_w, proj_w, ffn_w1, ffn_w2);
    // 2) LN1 -> fp16 activations
    ln_h_kernel<<<M_TOT / 8, 256>>>(x, ln1_g, ln1_b);
    // 3) QKV GEMM -> g_qkv (fp16)
    gemm_mma<false,true,false><<<dim3(6, 1600), 256, GEMM_SMEM>>>(
        ap, 256, WOFF_QKV, qkv_b, 768, nullptr, qkvp, nullptr);
    // 4) attention -> g_a (fp16)
    attn_kernel<<<NSEQ, 256, ATTN_SMEM>>>(logit_scale);
    // 5) proj GEMM + residual(x) -> d_out (fp32)
    gemm_mma<false,false,true><<<dim3(2, 1600), 256, GEMM_SMEM>>>(
        ap, 256, WOFF_PROJ, proj_b, 256, out, nullptr, x);
    // 6) LN2 -> fp16 activations
    ln_h_kernel<<<M_TOT / 8, 256>>>(out, ln2_g, ln2_b);
    // 7) FFN1 GEMM + GELU -> g_h (fp16)
    gemm_mma<true,true,false><<<dim3(8, 1600), 256, GEMM_SMEM>>>(
        ap, 256, WOFF_F1, ffn_b1, 1024, nullptr, hp, nullptr);
    // 8) FFN2 GEMM + residual -> d_out (final)
    gemm_mma<false,false,true><<<dim3(2, 1600), 256, GEMM_SMEM>>>(
        hp, 1024, WOFF_F2, ffn_b2, 256, out, nullptr, out);
}

// round 9
// speedup vs baseline: 7.7875x; 1.2537x over previous
#include <cuda_runtime.h>
#include <cuda_fp16.h>
#include <math.h>
#include <stdint.h>

// Problem dims: n = 8192 sequences, V=25 tokens, D=256, H=8, HD=32
#define NSEQ  8192
#define M_TOT 204800        // 8192*25, divisible by 128 -> 1600 M-tiles

// ---------------- device scratch (allocation-free: __device__ globals) -------
__device__ __half g_a[(size_t)M_TOT * 256];     // activations (fp16)
__device__ __half g_qkv[(size_t)M_TOT * 768];   // qkv out (fp16)
__device__ __half g_h[(size_t)M_TOT * 1024];    // ffn hidden (fp16)
// transposed weights: [qkv 768x256 | proj 256x256 | ffn1 1024x256 | ffn2 256x1024]
#define WOFF_QKV  0
#define WOFF_PROJ 196608
#define WOFF_F1   262144
#define WOFF_F2   524288
__device__ __half g_w[786432];

// ---------------- PTX helpers ------------------------------------------------
__device__ __forceinline__ uint32_t smem_u32(const void* p) {
    uint32_t a;
    asm("{ .reg .u64 t; cvta.to.shared.u64 t, %1; cvt.u32.u64 %0, t; }" : "=r"(a) : "l"(p));
    return a;
}
#define CP_COMMIT() asm volatile("cp.async.commit_group;" ::: "memory")
#define CP_WAIT2()  asm volatile("cp.async.wait_group 2;" ::: "memory")
__device__ __forceinline__ void cpa16(uint32_t dst, const void* src) {
    asm volatile("cp.async.cg.shared.global [%0], [%1], 16;" :: "r"(dst), "l"(src));
}
__device__ __forceinline__ void ldm_x4(uint32_t& r0, uint32_t& r1, uint32_t& r2, uint32_t& r3, uint32_t addr) {
    asm volatile("ldmatrix.sync.aligned.m8n8.x4.shared.b16 {%0,%1,%2,%3}, [%4];"
                 : "=r"(r0), "=r"(r1), "=r"(r2), "=r"(r3) : "r"(addr));
}
__device__ __forceinline__ void mma_fp16(float* d, const uint32_t* a, uint32_t b0, uint32_t b1) {
    asm volatile("mma.sync.aligned.m16n8k16.row.col.f32.f16.f16.f32 "
                 "{%0,%1,%2,%3},{%4,%5,%6,%7},{%8,%9},{%0,%1,%2,%3};"
                 : "+f"(d[0]), "+f"(d[1]), "+f"(d[2]), "+f"(d[3])
                 : "r"(a[0]), "r"(a[1]), "r"(a[2]), "r"(a[3]), "r"(b0), "r"(b1));
}
__device__ __forceinline__ float warp_sum(float v) {
#pragma unroll
    for (int o = 16; o > 0; o >>= 1) v += __shfl_xor_sync(0xffffffffu, v, o);
    return v;
}

// ---------------- weight prep: transpose to [N x K] fp16 ---------------------
__global__ void prep_w_kernel(const float* __restrict__ qkvw, const float* __restrict__ projw,
                              const float* __restrict__ f1w, const float* __restrict__ f2w) {
    int idx = blockIdx.x * 256 + threadIdx.x;
    if (idx >= 786432) return;
    const float* src; int K, N, local;
    if (idx < WOFF_PROJ)    { src = qkvw;  K = 256;  N = 768;  local = idx; }
    else if (idx < WOFF_F1) { src = projw; K = 256;  N = 256;  local = idx - WOFF_PROJ; }
    else if (idx < WOFF_F2) { src = f1w;   K = 256;  N = 1024; local = idx - WOFF_F1; }
    else                    { src = f2w;   K = 1024; N = 256;  local = idx - WOFF_F2; }
    int n = local / K, k = local % K;
    g_w[idx] = __float2half_rn(src[(size_t)k * N + n]);
}

// ---------------- LayerNorm -> fp16: one warp per row, float4 ----------------
__global__ void __launch_bounds__(256) ln_h_kernel(
    const float* __restrict__ in, const float* __restrict__ g, const float* __restrict__ b) {
    int row = blockIdx.x * 8 + (threadIdx.x >> 5);
    int lane = threadIdx.x & 31;
    const float4* rp4 = (const float4*)(in + (size_t)row * 256);
    float4 xv[2];
    xv[0] = rp4[lane]; xv[1] = rp4[lane + 32];
    float s1 = xv[0].x + xv[0].y + xv[0].z + xv[0].w + xv[1].x + xv[1].y + xv[1].z + xv[1].w;
    float s2 = xv[0].x*xv[0].x + xv[0].y*xv[0].y + xv[0].z*xv[0].z + xv[0].w*xv[0].w
             + xv[1].x*xv[1].x + xv[1].y*xv[1].y + xv[1].z*xv[1].z + xv[1].w*xv[1].w;
    s1 = warp_sum(s1); s2 = warp_sum(s2);
    float mean = s1 * (1.f / 256.f);
    float var = s2 * (1.f / 256.f) - mean * mean;
    float rs = rsqrtf(var + 1e-5f);
    __half* op = g_a + (size_t)row * 256;
#pragma unroll
    for (int u = 0; u < 2; u++) {
        int c4 = lane + 32 * u;
        float4 gg = ((const float4*)g)[c4];
        float4 bb = ((const float4*)b)[c4];
        float y0 = (xv[u].x - mean) * rs * gg.x + bb.x;
        float y1 = (xv[u].y - mean) * rs * gg.y + bb.y;
        float y2 = (xv[u].z - mean) * rs * gg.z + bb.z;
        float y3 = (xv[u].w - mean) * rs * gg.w + bb.w;
        __half2 h01 = __floats2half2_rn(y0, y1);
        __half2 h23 = __floats2half2_rn(y2, y3);
        *(uint2*)&op[c4 * 4] = make_uint2(*(uint32_t*)&h01, *(uint32_t*)&h23);
    }
}

// ---------------- HMMA fp16 GEMM: C[M_TOT x Ntot] = A @ Wt^T -----------------
// CTA 128x128, warp tile 64x32 (2x4 warps), K-tile 64, 3-stage cp.async.
#define ST_SZ   32768          // per stage: A 16KB + B 16KB
#define GEMM_SMEM (3 * ST_SZ)  // 96KB

__device__ __forceinline__ void load_tile(uint32_t stage_base,
    const __half* __restrict__ A, const __half* __restrict__ B,
    int K, int kk, int m0, int n0, int tid)
{
    uint32_t aB = stage_base;
    uint32_t bB = stage_base + 16384;
#pragma unroll
    for (int i = 0; i < 4; i++) {
        int idx = tid + i * 256;
        int r = idx >> 3, c = idx & 7;                 // row 0..127, 16B chunk 0..7
        uint32_t off = (uint32_t)(r * 128 + c * 16);
        uint32_t sw = off ^ ((uint32_t)(r & 7) << 4);  // SW128
        cpa16(aB + sw, A + (size_t)(m0 + r) * K + kk + c * 8);
    }
#pragma unroll
    for (int i = 0; i < 4; i++) {
        int idx = tid + i * 256;
        int r = idx >> 3, c = idx & 7;
        uint32_t off = (uint32_t)(r * 128 + c * 16);
        uint32_t sw = off ^ ((uint32_t)(r & 7) << 4);
        cpa16(bB + sw, B + (size_t)(n0 + r) * K + kk + c * 8);
    }
}

template<bool GELU, bool HALFOUT, bool RESID>
__global__ void __launch_bounds__(256, 2) gemm_mma(
    const __half* __restrict__ A, int K, int woff,
    const float* __restrict__ bias, int Ntot,
    float* __restrict__ outF, __half* __restrict__ outH,
    const float* __restrict__ resid)
{
    extern __shared__ char smem[];
    uint32_t sb = smem_u32(smem);
    const int tid = threadIdx.x, wid = tid >> 5, lane = tid & 31;
    const int wm = wid & 1, wn = wid >> 1;
    const int m0 = blockIdx.y * 128, n0 = blockIdx.x * 128;
    const int NT = K >> 6;                 // 4 or 16; always >= 3
    const __half* W = g_w + woff;

    float acc[4][4][4];
#pragma unroll
    for (int i = 0; i < 4; i++)
#pragma unroll
        for (int j = 0; j < 4; j++)
#pragma unroll
            for (int kq = 0; kq < 4; kq++) acc[i][j][kq] = 0.f;

    load_tile(sb,             A, W, K, 0,   m0, n0, tid); CP_COMMIT();
    load_tile(sb + ST_SZ,     A, W, K, 64,  m0, n0, tid); CP_COMMIT();
    load_tile(sb + 2 * ST_SZ, A, W, K, 128, m0, n0, tid); CP_COMMIT();

    // per-lane ldmatrix geometry
    const int grp = lane >> 3, lr = lane & 7;
    const int a_row_b = wm * 64 + (grp & 1) * 8 + lr;   // + mf*16
    const int a_kb    = (grp >> 1) * 16;                // bytes
    const int b_row_b = wn * 32 + (grp >> 1) * 8 + lr;  // + np*16
    const int b_kb    = (grp & 1) * 16;                 // bytes

    int s = 0;
    for (int kt = 0; kt < NT; kt++) {
        CP_WAIT2();
        __syncthreads();

        const uint32_t aBase = sb + s * ST_SZ;
        const uint32_t bBase = aBase + 16384;
#pragma unroll
        for (int ks = 0; ks < 4; ks++) {
            const int kb = ks * 32;  // bytes into the 128B row
            uint32_t af[4][4];
#pragma unroll
            for (int mf = 0; mf < 4; mf++) {
                int row = a_row_b + mf * 16;
                uint32_t off = (uint32_t)(row * 128 + kb + a_kb);
                uint32_t addr = aBase + (off ^ ((uint32_t)(row & 7) << 4));
                ldm_x4(af[mf][0], af[mf][1], af[mf][2], af[mf][3], addr);
            }
            uint32_t bf[2][4];
#pragma unroll
            for (int np = 0; np < 2; np++) {
                int row = b_row_b + np * 16;
                uint32_t off = (uint32_t)(row * 128 + kb + b_kb);
                uint32_t addr = bBase + (off ^ ((uint32_t)(row & 7) << 4));
                ldm_x4(bf[np][0], bf[np][1], bf[np][2], bf[np][3], addr);
            }
#pragma unroll
            for (int mf = 0; mf < 4; mf++)
#pragma unroll
                for (int nf = 0; nf < 4; nf++)
                    mma_fp16(acc[mf][nf], af[mf], bf[nf >> 1][(nf & 1) * 2], bf[nf >> 1][(nf & 1) * 2 + 1]);
        }
        __syncthreads();
        if (kt + 3 < NT)
            load_tile(sb + s * ST_SZ, A, W, K, (kt + 3) * 64, m0, n0, tid);
        CP_COMMIT();
        if (++s == 3) s = 0;
    }

    // -------- epilogue --------
    const int qr = lane >> 2;            // 0..7
    const int qc = (lane & 3) * 2;       // 0,2,4,6
#pragma unroll
    for (int mf = 0; mf < 4; mf++) {
#pragma unroll
        for (int nf = 0; nf < 4; nf++) {
            int C = n0 + wn * 32 + nf * 8 + qc;
            float b0 = __ldg(&bias[C]), b1 = __ldg(&bias[C + 1]);
#pragma unroll
            for (int half_ = 0; half_ < 2; half_++) {
                int R = m0 + wm * 64 + mf * 16 + qr + half_ * 8;
                float v0 = acc[mf][nf][half_ * 2 + 0] + b0;
                float v1 = acc[mf][nf][half_ * 2 + 1] + b1;
                if (GELU) {
                    const float is2 = 0.70710678118654752f;
                    v0 = 0.5f * v0 * (1.0f + erff(v0 * is2));
                    v1 = 0.5f * v1 * (1.0f + erff(v1 * is2));
                }
                size_t gidx = (size_t)R * Ntot + C;
                if (RESID) {
                    float2 rv = *(const float2*)&resid[gidx];
                    v0 += rv.x; v1 += rv.y;
                }
                if (HALFOUT) {
                    *(__half2*)&outH[gidx] = __floats2half2_rn(v0, v1);
                } else {
                    *(float2*)&outF[gidx] = make_float2(v0, v1);
                }
            }
        }
    }
}

// ---------------- attention: CTA per sequence, warp = head ------------------
// No serial warp-reduction chains: all reductions are per-lane register loops.
#define ATTN_SMEM ((19200 + 8 * 640) * 4)   // qkv 25x768 fp32 + probs 8x640
__global__ void __launch_bounds__(256, 2) attn_kernel(const float* __restrict__ logit_scale) {
    extern __shared__ float sq[];
    float* sp = sq + 19200;
    const int tid = threadIdx.x, h = tid >> 5, lane = tid & 31;
    const size_t n = blockIdx.x;
    const __half2* qkv = (const __half2*)(g_qkv + n * 19200);
    for (int i = tid; i < 9600; i += 256) {
        float2 f = __half22float2(qkv[i]);
        sq[2 * i] = f.x; sq[2 * i + 1] = f.y;
    }
    __syncthreads();

    const float* q = sq + h * 32;          // row stride 768
    const float* k = sq + 256 + h * 32;
    const float* v = sq + 512 + h * 32;
    const float LOG100 = 4.6051701859880914f;
    const float scale = __expf(fminf(logit_scale[h], LOG100)) * 0.17677669529663687f; // fold 1/sqrt(32)

    // norms: lane i owns row i (rotated d -> conflict-free)
    float nq = 0.f, nk = 0.f;
    if (lane < 25) {
#pragma unroll
        for (int dd = 0; dd < 32; dd++) {
            int d = (dd + lane) & 31;
            float a = q[lane * 768 + d]; nq += a * a;
            float b = k[lane * 768 + d]; nk += b * b;
        }
    }
    float nqr = scale / fmaxf(sqrtf(nq), 1e-12f);
    float nkr = 1.0f / fmaxf(sqrtf(nk), 1e-12f);

    // logits (scaled): lane j computes column j of row i
    float* myp = sp + h * 640;
    for (int i = 0; i < 25; i++) {
        float nqi = __shfl_sync(0xffffffffu, nqr, i);
        if (lane < 25) {
            float dot = 0.f;
#pragma unroll
            for (int dd = 0; dd < 32; dd++) {
                int d = (dd + lane) & 31;
                dot += q[i * 768 + d] * k[lane * 768 + d];
            }
            myp[i * 25 + lane] = dot * nqi * nkr;
        }
    }
    __syncwarp();

    // softmax: lane i owns row i, fully in registers (stride 25 -> conflict-free)
    if (lane < 25) {
        float r[25];
        float mx = -INFINITY;
#pragma unroll
        for (int j = 0; j < 25; j++) { r[j] = myp[lane * 25 + j]; mx = fmaxf(mx, r[j]); }
        float s = 0.f;
#pragma unroll
        for (int j = 0; j < 25; j++) { r[j] = __expf(r[j] - mx); s += r[j]; }
        float inv = 1.0f / s;
#pragma unroll
        for (int j = 0; j < 25; j++) myp[lane * 25 + j] = r[j] * inv;
    }
    __syncwarp();

    // AV: lane = d; v column resident in registers, probs via broadcast LDS
    float vreg[25];
#pragma unroll
    for (int j = 0; j < 25; j++) vreg[j] = v[j * 768 + lane];
    for (int i = 0; i < 25; i++) {
        float o = 0.f;
#pragma unroll
        for (int j = 0; j < 25; j++) o += myp[i * 25 + j] * vreg[j];
        g_a[(n * 25 + i) * 256 + h * 32 + lane] = __float2half_rn(o);
    }
}

// ---------------- launch -----------------------------------------------------
extern "C" void kernel_launch(void* const* d_in, const int* in_sizes, int n_in,
                              void* d_out, int out_size)
{
    const float* x           = (const float*)d_in[0];
    const float* ln1_g       = (const float*)d_in[1];
    const float* ln1_b       = (const float*)d_in[2];
    const float* qkv_w       = (const float*)d_in[3];
    const float* qkv_b       = (const float*)d_in[4];
    const float* proj_w      = (const float*)d_in[5];
    const float* proj_b      = (const float*)d_in[6];
    const float* logit_scale = (const float*)d_in[7];
    const float* ln2_g       = (const float*)d_in[8];
    const float* ln2_b       = (const float*)d_in[9];
    const float* ffn_w1      = (const float*)d_in[10];
    const float* ffn_b1      = (const float*)d_in[11];
    const float* ffn_w2      = (const float*)d_in[12];
    const float* ffn_b2      = (const float*)d_in[13];
    float* out = (float*)d_out;

    cudaFuncSetAttribute(gemm_mma<false,true ,false>, cudaFuncAttributeMaxDynamicSharedMemorySize, GEMM_SMEM);
    cudaFuncSetAttribute(gemm_mma<false,false,true >, cudaFuncAttributeMaxDynamicSharedMemorySize, GEMM_SMEM);
    cudaFuncSetAttribute(gemm_mma<true ,true ,false>, cudaFuncAttributeMaxDynamicSharedMemorySize, GEMM_SMEM);
    cudaFuncSetAttribute(attn_kernel, cudaFuncAttributeMaxDynamicSharedMemorySize, ATTN_SMEM);

    __half *ap, *qkvp, *hp;
    cudaGetSymbolAddress((void**)&ap,   g_a);
    cudaGetSymbolAddress((void**)&qkvp, g_qkv);
    cudaGetSymbolAddress((void**)&hp,   g_h);

    // 1) weight transpose -> fp16
    prep_w_kernel<<<3072, 256>>>(qkv_w, proj_w, ffn_w1, ffn_w2);
    // 2) LN1 -> fp16 activations
    ln_h_kernel<<<M_TOT / 8, 256>>>(x, ln1_g, ln1_b);
    // 3) QKV GEMM -> g_qkv (fp16)
    gemm_mma<false,true,false><<<dim3(6, 1600), 256, GEMM_SMEM>>>(
        ap, 256, WOFF_QKV, qkv_b, 768, nullptr, qkvp, nullptr);
    // 4) attention -> g_a (fp16)
    attn_kernel<<<NSEQ, 256, ATTN_SMEM>>>(logit_scale);
    // 5) proj GEMM + residual(x) -> d_out (fp32)
    gemm_mma<false,false,true><<<dim3(2, 1600), 256, GEMM_SMEM>>>(
        ap, 256, WOFF_PROJ, proj_b, 256, out, nullptr, x);
    // 6) LN2 -> fp16 activations
    ln_h_kernel<<<M_TOT / 8, 256>>>(out, ln2_g, ln2_b);
    // 7) FFN1 GEMM + GELU -> g_h (fp16)
    gemm_mma<true,true,false><<<dim3(8, 1600), 256, GEMM_SMEM>>>(
        ap, 256, WOFF_F1, ffn_b1, 1024, nullptr, hp, nullptr);
    // 8) FFN2 GEMM + residual -> d_out (final)
    gemm_mma<false,false,true><<<dim3(2, 1600), 256, GEMM_SMEM>>>(
        hp, 1024, WOFF_F2, ffn_b2, 256, out, nullptr, out);
}

// round 11
// speedup vs baseline: 10.0310x; 1.2881x over previous
#include <cuda_runtime.h>
#include <cuda_fp16.h>
#include <math.h>
#include <stdint.h>

// Problem dims: n = 8192 sequences, V=25 tokens, D=256, H=8, HD=32
#define NSEQ  8192
#define M_TOT 204800        // 8192*25, divisible by 128 -> 1600 M-tiles

// ---------------- device scratch (allocation-free: __device__ globals) -------
__device__ __half g_a[(size_t)M_TOT * 256];     // activations (fp16)
__device__ __half g_qkv[(size_t)M_TOT * 768];   // qkv out (fp16)
__device__ __half g_h[(size_t)M_TOT * 1024];    // ffn hidden (fp16)
// transposed weights: [qkv 768x256 | proj 256x256 | ffn1 1024x256 | ffn2 256x1024]
#define WOFF_QKV  0
#define WOFF_PROJ 196608
#define WOFF_F1   262144
#define WOFF_F2   524288
__device__ __half g_w[786432];

// ---------------- PTX helpers ------------------------------------------------
__device__ __forceinline__ uint32_t smem_u32(const void* p) {
    uint32_t a;
    asm("{ .reg .u64 t; cvta.to.shared.u64 t, %1; cvt.u32.u64 %0, t; }" : "=r"(a) : "l"(p));
    return a;
}
#define CP_COMMIT() asm volatile("cp.async.commit_group;" ::: "memory")
#define CP_WAIT2()  asm volatile("cp.async.wait_group 2;" ::: "memory")
__device__ __forceinline__ void cpa16(uint32_t dst, const void* src) {
    asm volatile("cp.async.cg.shared.global [%0], [%1], 16;" :: "r"(dst), "l"(src));
}
__device__ __forceinline__ void ldm_x4(uint32_t& r0, uint32_t& r1, uint32_t& r2, uint32_t& r3, uint32_t addr) {
    asm volatile("ldmatrix.sync.aligned.m8n8.x4.shared.b16 {%0,%1,%2,%3}, [%4];"
                 : "=r"(r0), "=r"(r1), "=r"(r2), "=r"(r3) : "r"(addr));
}
__device__ __forceinline__ void ldm_x4_t(uint32_t& r0, uint32_t& r1, uint32_t& r2, uint32_t& r3, uint32_t addr) {
    asm volatile("ldmatrix.sync.aligned.m8n8.x4.trans.shared.b16 {%0,%1,%2,%3}, [%4];"
                 : "=r"(r0), "=r"(r1), "=r"(r2), "=r"(r3) : "r"(addr));
}
__device__ __forceinline__ void mma_fp16(float* d, const uint32_t* a, uint32_t b0, uint32_t b1) {
    asm volatile("mma.sync.aligned.m16n8k16.row.col.f32.f16.f16.f32 "
                 "{%0,%1,%2,%3},{%4,%5,%6,%7},{%8,%9},{%0,%1,%2,%3};"
                 : "+f"(d[0]), "+f"(d[1]), "+f"(d[2]), "+f"(d[3])
                 : "r"(a[0]), "r"(a[1]), "r"(a[2]), "r"(a[3]), "r"(b0), "r"(b1));
}
__device__ __forceinline__ float warp_sum(float v) {
#pragma unroll
    for (int o = 16; o > 0; o >>= 1) v += __shfl_xor_sync(0xffffffffu, v, o);
    return v;
}
__device__ __forceinline__ float hsq(uint32_t u) {   // sum of squares of packed half2
    float2 f = __half22float2(*(__half2*)&u);
    return f.x * f.x + f.y * f.y;
}

// ---------------- weight prep: transpose to [N x K] fp16 ---------------------
__global__ void prep_w_kernel(const float* __restrict__ qkvw, const float* __restrict__ projw,
                              const float* __restrict__ f1w, const float* __restrict__ f2w) {
    int idx = blockIdx.x * 256 + threadIdx.x;
    if (idx >= 786432) return;
    const float* src; int K, N, local;
    if (idx < WOFF_PROJ)    { src = qkvw;  K = 256;  N = 768;  local = idx; }
    else if (idx < WOFF_F1) { src = projw; K = 256;  N = 256;  local = idx - WOFF_PROJ; }
    else if (idx < WOFF_F2) { src = f1w;   K = 256;  N = 1024; local = idx - WOFF_F1; }
    else                    { src = f2w;   K = 1024; N = 256;  local = idx - WOFF_F2; }
    int n = local / K, k = local % K;
    g_w[idx] = __float2half_rn(src[(size_t)k * N + n]);
}

// ---------------- LayerNorm -> fp16: one warp per row, float4 ----------------
__global__ void __launch_bounds__(256) ln_h_kernel(
    const float* __restrict__ in, const float* __restrict__ g, const float* __restrict__ b) {
    int row = blockIdx.x * 8 + (threadIdx.x >> 5);
    int lane = threadIdx.x & 31;
    const float4* rp4 = (const float4*)(in + (size_t)row * 256);
    float4 xv[2];
    xv[0] = rp4[lane]; xv[1] = rp4[lane + 32];
    float s1 = xv[0].x + xv[0].y + xv[0].z + xv[0].w + xv[1].x + xv[1].y + xv[1].z + xv[1].w;
    float s2 = xv[0].x*xv[0].x + xv[0].y*xv[0].y + xv[0].z*xv[0].z + xv[0].w*xv[0].w
             + xv[1].x*xv[1].x + xv[1].y*xv[1].y + xv[1].z*xv[1].z + xv[1].w*xv[1].w;
    s1 = warp_sum(s1); s2 = warp_sum(s2);
    float mean = s1 * (1.f / 256.f);
    float var = s2 * (1.f / 256.f) - mean * mean;
    float rs = rsqrtf(var + 1e-5f);
    __half* op = g_a + (size_t)row * 256;
#pragma unroll
    for (int u = 0; u < 2; u++) {
        int c4 = lane + 32 * u;
        float4 gg = ((const float4*)g)[c4];
        float4 bb = ((const float4*)b)[c4];
        float y0 = (xv[u].x - mean) * rs * gg.x + bb.x;
        float y1 = (xv[u].y - mean) * rs * gg.y + bb.y;
        float y2 = (xv[u].z - mean) * rs * gg.z + bb.z;
        float y3 = (xv[u].w - mean) * rs * gg.w + bb.w;
        __half2 h01 = __floats2half2_rn(y0, y1);
        __half2 h23 = __floats2half2_rn(y2, y3);
        *(uint2*)&op[c4 * 4] = make_uint2(*(uint32_t*)&h01, *(uint32_t*)&h23);
    }
}

// ---------------- HMMA fp16 GEMM: C[M_TOT x Ntot] = A @ Wt^T -----------------
// CTA 128x128, warp tile 64x32 (2x4 warps), K-tile 64, 3-stage cp.async.
#define ST_SZ   32768          // per stage: A 16KB + B 16KB
#define GEMM_SMEM (3 * ST_SZ)  // 96KB

__device__ __forceinline__ void load_tile(uint32_t stage_base,
    const __half* __restrict__ A, const __half* __restrict__ B,
    int K, int kk, int m0, int n0, int tid)
{
    uint32_t aB = stage_base;
    uint32_t bB = stage_base + 16384;
#pragma unroll
    for (int i = 0; i < 4; i++) {
        int idx = tid + i * 256;
        int r = idx >> 3, c = idx & 7;                 // row 0..127, 16B chunk 0..7
        uint32_t off = (uint32_t)(r * 128 + c * 16);
        uint32_t sw = off ^ ((uint32_t)(r & 7) << 4);  // SW128
        cpa16(aB + sw, A + (size_t)(m0 + r) * K + kk + c * 8);
    }
#pragma unroll
    for (int i = 0; i < 4; i++) {
        int idx = tid + i * 256;
        int r = idx >> 3, c = idx & 7;
        uint32_t off = (uint32_t)(r * 128 + c * 16);
        uint32_t sw = off ^ ((uint32_t)(r & 7) << 4);
        cpa16(bB + sw, B + (size_t)(n0 + r) * K + kk + c * 8);
    }
}

template<bool GELU, bool HALFOUT, bool RESID>
__global__ void __launch_bounds__(256, 2) gemm_mma(
    const __half* __restrict__ A, int K, int woff,
    const float* __restrict__ bias, int Ntot,
    float* __restrict__ outF, __half* __restrict__ outH,
    const float* __restrict__ resid)
{
    extern __shared__ char smem[];
    uint32_t sb = smem_u32(smem);
    const int tid = threadIdx.x, wid = tid >> 5, lane = tid & 31;
    const int wm = wid & 1, wn = wid >> 1;
    const int m0 = blockIdx.y * 128, n0 = blockIdx.x * 128;
    const int NT = K >> 6;
    const __half* W = g_w + woff;

    float acc[4][4][4];
#pragma unroll
    for (int i = 0; i < 4; i++)
#pragma unroll
        for (int j = 0; j < 4; j++)
#pragma unroll
            for (int kq = 0; kq < 4; kq++) acc[i][j][kq] = 0.f;

    load_tile(sb,             A, W, K, 0,   m0, n0, tid); CP_COMMIT();
    load_tile(sb + ST_SZ,     A, W, K, 64,  m0, n0, tid); CP_COMMIT();
    load_tile(sb + 2 * ST_SZ, A, W, K, 128, m0, n0, tid); CP_COMMIT();

    const int grp = lane >> 3, lr = lane & 7;
    const int a_row_b = wm * 64 + (grp & 1) * 8 + lr;   // + mf*16
    const int a_kb    = (grp >> 1) * 16;                // bytes
    const int b_row_b = wn * 32 + (grp >> 1) * 8 + lr;  // + np*16
    const int b_kb    = (grp & 1) * 16;                 // bytes

    int s = 0;
    for (int kt = 0; kt < NT; kt++) {
        CP_WAIT2();
        __syncthreads();

        const uint32_t aBase = sb + s * ST_SZ;
        const uint32_t bBase = aBase + 16384;
#pragma unroll
        for (int ks = 0; ks < 4; ks++) {
            const int kb = ks * 32;
            uint32_t af[4][4];
#pragma unroll
            for (int mf = 0; mf < 4; mf++) {
                int row = a_row_b + mf * 16;
                uint32_t off = (uint32_t)(row * 128 + kb + a_kb);
                uint32_t addr = aBase + (off ^ ((uint32_t)(row & 7) << 4));
                ldm_x4(af[mf][0], af[mf][1], af[mf][2], af[mf][3], addr);
            }
            uint32_t bf[2][4];
#pragma unroll
            for (int np = 0; np < 2; np++) {
                int row = b_row_b + np * 16;
                uint32_t off = (uint32_t)(row * 128 + kb + b_kb);
                uint32_t addr = bBase + (off ^ ((uint32_t)(row & 7) << 4));
                ldm_x4(bf[np][0], bf[np][1], bf[np][2], bf[np][3], addr);
            }
#pragma unroll
            for (int mf = 0; mf < 4; mf++)
#pragma unroll
                for (int nf = 0; nf < 4; nf++)
                    mma_fp16(acc[mf][nf], af[mf], bf[nf >> 1][(nf & 1) * 2], bf[nf >> 1][(nf & 1) * 2 + 1]);
        }
        __syncthreads();
        if (kt + 3 < NT)
            load_tile(sb + s * ST_SZ, A, W, K, (kt + 3) * 64, m0, n0, tid);
        CP_COMMIT();
        if (++s == 3) s = 0;
    }

    const int qr = lane >> 2;
    const int qc = (lane & 3) * 2;
#pragma unroll
    for (int mf = 0; mf < 4; mf++) {
#pragma unroll
        for (int nf = 0; nf < 4; nf++) {
            int C = n0 + wn * 32 + nf * 8 + qc;
            float b0 = __ldg(&bias[C]), b1 = __ldg(&bias[C + 1]);
#pragma unroll
            for (int half_ = 0; half_ < 2; half_++) {
                int R = m0 + wm * 64 + mf * 16 + qr + half_ * 8;
                float v0 = acc[mf][nf][half_ * 2 + 0] + b0;
                float v1 = acc[mf][nf][half_ * 2 + 1] + b1;
                if (GELU) {
                    const float is2 = 0.70710678118654752f;
                    v0 = 0.5f * v0 * (1.0f + erff(v0 * is2));
                    v1 = 0.5f * v1 * (1.0f + erff(v1 * is2));
                }
                size_t gidx = (size_t)R * Ntot + C;
                if (RESID) {
                    float2 rv = *(const float2*)&resid[gidx];
                    v0 += rv.x; v1 += rv.y;
                }
                if (HALFOUT) {
                    *(__half2*)&outH[gidx] = __floats2half2_rn(v0, v1);
                } else {
                    *(float2*)&outF[gidx] = make_float2(v0, v1);
                }
            }
        }
    }
}

// ---------------- tensor-core attention: CTA per sequence, warp = head -------
// q/k/v per head staged in 64B-row swizzled fp16 buffers (rows 25..31 zero).
// QK^T and P@V via mma.m16n8k16; norms from fragments; softmax in fragments.
#define ATTN_SMEM 49152   // 8 heads * 3 * 32x32 fp16 (2KB each)
__device__ __forceinline__ uint32_t swz(int row, int byte_) {
    return (uint32_t)((row * 64 + byte_) ^ ((row & 3) << 4));
}
__global__ void __launch_bounds__(256, 2) attn_kernel(const float* __restrict__ logit_scale) {
    extern __shared__ char smem[];
    uint32_t sb = smem_u32(smem);
    const int tid = threadIdx.x, hd = tid >> 5, lane = tid & 31;
    const size_t n = blockIdx.x;

    // ---- fill swizzled q/k/v buffers (3072 16B chunks) ----
#pragma unroll
    for (int i = 0; i < 12; i++) {
        int idx = tid + i * 256;
        int c16 = idx & 3, h = (idx >> 2) & 7, r = (idx >> 5) & 31, w = idx >> 10;
        uint32_t dst = sb + (uint32_t)(h * 3 + w) * 2048 + swz(r, c16 * 16);
        if (r < 25) {
            const __half* src = g_qkv + (n * 25 + r) * 768 + w * 256 + h * 32 + c16 * 8;
            uint4 v = *(const uint4*)src;
            asm volatile("st.shared.v4.b32 [%0], {%1,%2,%3,%4};" :: "r"(dst), "r"(v.x), "r"(v.y), "r"(v.z), "r"(v.w));
        } else {
            asm volatile("st.shared.v4.b32 [%0], {%1,%1,%1,%1};" :: "r"(dst), "r"(0u));
        }
    }
    __syncthreads();

    const uint32_t qb = sb + (uint32_t)hd * 3 * 2048;
    const uint32_t kb = qb + 2048;
    const uint32_t vb = qb + 4096;
    const int grp = lane >> 3, lr = lane & 7;
    const int qr = lane >> 2, qc = lane & 3;

    // ---- load Q (A-frags) and K (B-frags) ----
    uint32_t af[2][2][4];   // [mf][ks]
#pragma unroll
    for (int mf = 0; mf < 2; mf++)
#pragma unroll
        for (int ks = 0; ks < 2; ks++) {
            int row = mf * 16 + (grp & 1) * 8 + lr;
            uint32_t addr = qb + swz(row, (grp >> 1) * 16 + ks * 32);
            ldm_x4(af[mf][ks][0], af[mf][ks][1], af[mf][ks][2], af[mf][ks][3], addr);
        }
    uint32_t kf[2][2][4];   // [np][ks]
#pragma unroll
    for (int np = 0; np < 2; np++)
#pragma unroll
        for (int ks = 0; ks < 2; ks++) {
            int row = np * 16 + (grp >> 1) * 8 + lr;
            uint32_t addr = kb + swz(row, (grp & 1) * 16 + ks * 32);
            ldm_x4(kf[np][ks][0], kf[np][ks][1], kf[np][ks][2], kf[np][ks][3], addr);
        }

    // ---- QK^T ----
    float acc[2][4][4];
#pragma unroll
    for (int mf = 0; mf < 2; mf++)
#pragma unroll
        for (int nf = 0; nf < 4; nf++)
#pragma unroll
            for (int u = 0; u < 4; u++) acc[mf][nf][u] = 0.f;
#pragma unroll
    for (int ks = 0; ks < 2; ks++)
#pragma unroll
        for (int mf = 0; mf < 2; mf++)
#pragma unroll
            for (int nf = 0; nf < 4; nf++)
                mma_fp16(acc[mf][nf], af[mf][ks], kf[nf >> 1][ks][(nf & 1) * 2], kf[nf >> 1][ks][(nf & 1) * 2 + 1]);

    // ---- norms from fragments (rows qr+{0,8,16,24}; cols qr + {0,8,16,24}) ----
    const float LOG100 = 4.6051701859880914f;
    const float stot = __expf(fminf(__ldg(&logit_scale[hd]), LOG100)) * 0.17677669529663687f;

    float nqp[4], nkp[4];
#pragma unroll
    for (int i = 0; i < 4; i++) {
        int mf = i >> 1, h2 = i & 1;
        nqp[i] = hsq(af[mf][0][h2]) + hsq(af[mf][0][h2 + 2]) + hsq(af[mf][1][h2]) + hsq(af[mf][1][h2 + 2]);
    }
#pragma unroll
    for (int i = 0; i < 4; i++) {
        int np = i >> 1, t = i & 1;
        nkp[i] = hsq(kf[np][0][2 * t]) + hsq(kf[np][0][2 * t + 1]) + hsq(kf[np][1][2 * t]) + hsq(kf[np][1][2 * t + 1]);
    }
#pragma unroll
    for (int o = 1; o <= 2; o <<= 1) {
#pragma unroll
        for (int i = 0; i < 4; i++) {
            nqp[i] += __shfl_xor_sync(0xffffffffu, nqp[i], o);
            nkp[i] += __shfl_xor_sync(0xffffffffu, nkp[i], o);
        }
    }
    float nqr4[4], nkr4[4];
#pragma unroll
    for (int i = 0; i < 4; i++) {
        nqr4[i] = stot / fmaxf(sqrtf(nqp[i]), 1e-12f);
        nkr4[i] = 1.0f / fmaxf(sqrtf(nkp[i]), 1e-12f);
    }
    // redistribute col norms: col c = nf*8 + 2qc + u lives at lane (c&7)*4, reg nf
    float skc[4][2];
#pragma unroll
    for (int nf = 0; nf < 4; nf++)
#pragma unroll
        for (int u = 0; u < 2; u++)
            skc[nf][u] = __shfl_sync(0xffffffffu, nkr4[nf], ((2 * qc + u) & 7) << 2);

    // ---- scale + mask + softmax (per row-half) ----
#pragma unroll
    for (int mf = 0; mf < 2; mf++)
#pragma unroll
        for (int h2 = 0; h2 < 2; h2++) {
            float sq_ = nqr4[mf * 2 + h2];
            float vals[8];
#pragma unroll
            for (int nf = 0; nf < 4; nf++)
#pragma unroll
                for (int u = 0; u < 2; u++) {
                    float v = acc[mf][nf][h2 * 2 + u] * sq_ * skc[nf][u];
                    if (nf == 3 && (24 + 2 * qc + u) >= 25) v = -1e30f;
                    vals[nf * 2 + u] = v;
                }
            float m = vals[0];
#pragma unroll
            for (int j = 1; j < 8; j++) m = fmaxf(m, vals[j]);
            m = fmaxf(m, __shfl_xor_sync(0xffffffffu, m, 1));
            m = fmaxf(m, __shfl_xor_sync(0xffffffffu, m, 2));
            float s = 0.f;
#pragma unroll
            for (int j = 0; j < 8; j++) { vals[j] = __expf(vals[j] - m); s += vals[j]; }
            s += __shfl_xor_sync(0xffffffffu, s, 1);
            s += __shfl_xor_sync(0xffffffffu, s, 2);
            float inv = 1.0f / s;
#pragma unroll
            for (int nf = 0; nf < 4; nf++)
#pragma unroll
                for (int u = 0; u < 2; u++)
                    acc[mf][nf][h2 * 2 + u] = vals[nf * 2 + u] * inv;
        }

    // ---- P (C-frags) -> A-frags ----
    uint32_t pa[2][2][4];   // [mf][ks]
#pragma unroll
    for (int mf = 0; mf < 2; mf++)
#pragma unroll
        for (int ks = 0; ks < 2; ks++) {
            __half2 h0 = __floats2half2_rn(acc[mf][2 * ks][0], acc[mf][2 * ks][1]);
            __half2 h1 = __floats2half2_rn(acc[mf][2 * ks][2], acc[mf][2 * ks][3]);
            __half2 h2_ = __floats2half2_rn(acc[mf][2 * ks + 1][0], acc[mf][2 * ks + 1][1]);
            __half2 h3 = __floats2half2_rn(acc[mf][2 * ks + 1][2], acc[mf][2 * ks + 1][3]);
            pa[mf][ks][0] = *(uint32_t*)&h0; pa[mf][ks][1] = *(uint32_t*)&h1;
            pa[mf][ks][2] = *(uint32_t*)&h2_; pa[mf][ks][3] = *(uint32_t*)&h3;
        }

    // ---- V as B-frags via ldmatrix.trans (V stored j-rows, need d-major) ----
    uint32_t vf[2][2][4];   // [ks][np]
#pragma unroll
    for (int ks = 0; ks < 2; ks++)
#pragma unroll
        for (int np = 0; np < 2; np++) {
            int row = ks * 16 + (grp & 1) * 8 + lr;
            uint32_t addr = vb + swz(row, (grp >> 1) * 16 + np * 32);
            ldm_x4_t(vf[ks][np][0], vf[ks][np][1], vf[ks][np][2], vf[ks][np][3], addr);
        }

    // ---- P @ V ----
    float oacc[2][4][4];
#pragma unroll
    for (int mf = 0; mf < 2; mf++)
#pragma unroll
        for (int nf = 0; nf < 4; nf++)
#pragma unroll
            for (int u = 0; u < 4; u++) oacc[mf][nf][u] = 0.f;
#pragma unroll
    for (int ks = 0; ks < 2; ks++)
#pragma unroll
        for (int mf = 0; mf < 2; mf++)
#pragma unroll
            for (int nf = 0; nf < 4; nf++)
                mma_fp16(oacc[mf][nf], pa[mf][ks], vf[ks][nf >> 1][(nf & 1) * 2], vf[ks][nf >> 1][(nf & 1) * 2 + 1]);

    // ---- store rows < 25 ----
#pragma unroll
    for (int mf = 0; mf < 2; mf++)
#pragma unroll
        for (int h2 = 0; h2 < 2; h2++) {
            int R = mf * 16 + h2 * 8 + qr;
            if (R < 25) {
#pragma unroll
                for (int nf = 0; nf < 4; nf++) {
                    int d = nf * 8 + 2 * qc;
                    __half2 hv = __floats2half2_rn(oacc[mf][nf][h2 * 2], oacc[mf][nf][h2 * 2 + 1]);
                    *(__half2*)&g_a[(n * 25 + R) * 256 + hd * 32 + d] = hv;
                }
            }
        }
}

// ---------------- launch -----------------------------------------------------
extern "C" void kernel_launch(void* const* d_in, const int* in_sizes, int n_in,
                              void* d_out, int out_size)
{
    const float* x           = (const float*)d_in[0];
    const float* ln1_g       = (const float*)d_in[1];
    const float* ln1_b       = (const float*)d_in[2];
    const float* qkv_w       = (const float*)d_in[3];
    const float* qkv_b       = (const float*)d_in[4];
    const float* proj_w      = (const float*)d_in[5];
    const float* proj_b      = (const float*)d_in[6];
    const float* logit_scale = (const float*)d_in[7];
    const float* ln2_g       = (const float*)d_in[8];
    const float* ln2_b       = (const float*)d_in[9];
    const float* ffn_w1      = (const float*)d_in[10];
    const float* ffn_b1      = (const float*)d_in[11];
    const float* ffn_w2      = (const float*)d_in[12];
    const float* ffn_b2      = (const float*)d_in[13];
    float* out = (float*)d_out;

    cudaFuncSetAttribute(gemm_mma<false,true ,false>, cudaFuncAttributeMaxDynamicSharedMemorySize, GEMM_SMEM);
    cudaFuncSetAttribute(gemm_mma<false,false,true >, cudaFuncAttributeMaxDynamicSharedMemorySize, GEMM_SMEM);
    cudaFuncSetAttribute(gemm_mma<true ,true ,false>, cudaFuncAttributeMaxDynamicSharedMemorySize, GEMM_SMEM);
    cudaFuncSetAttribute(attn_kernel, cudaFuncAttributeMaxDynamicSharedMemorySize, ATTN_SMEM);

    __half *ap, *qkvp, *hp;
    cudaGetSymbolAddress((void**)&ap,   g_a);
    cudaGetSymbolAddress((void**)&qkvp, g_qkv);
    cudaGetSymbolAddress((void**)&hp,   g_h);

    // 1) weight transpose -> fp16
    prep_w_kernel<<<3072, 256>>>(qkv_w, proj_w, ffn_w1, ffn_w2);
    // 2) LN1 -> fp16 activations
    ln_h_kernel<<<M_TOT / 8, 256>>>(x, ln1_g, ln1_b);
    // 3) QKV GEMM -> g_qkv (fp16)
    gemm_mma<false,true,false><<<dim3(6, 1600), 256, GEMM_SMEM>>>(
        ap, 256, WOFF_QKV, qkv_b, 768, nullptr, qkvp, nullptr);
    // 4) attention -> g_a (fp16)
    attn_kernel<<<NSEQ, 256, ATTN_SMEM>>>(logit_scale);
    // 5) proj GEMM + residual(x) -> d_out (fp32)
    gemm_mma<false,false,true><<<dim3(2, 1600), 256, GEMM_SMEM>>>(
        ap, 256, WOFF_PROJ, proj_b, 256, out, nullptr, x);
    // 6) LN2 -> fp16 activations
    ln_h_kernel<<<M_TOT / 8, 256>>>(out, ln2_g, ln2_b);
    // 7) FFN1 GEMM + GELU -> g_h (fp16)
    gemm_mma<true,true,false><<<dim3(8, 1600), 256, GEMM_SMEM>>>(
        ap, 256, WOFF_F1, ffn_b1, 1024, nullptr, hp, nullptr);
    // 8) FFN2 GEMM + residual -> d_out (final)
    gemm_mma<false,false,true><<<dim3(2, 1600), 256, GEMM_SMEM>>>(
        hp, 1024, WOFF_F2, ffn_b2, 256, out, nullptr, out);
}

// round 12
// speedup vs baseline: 10.6319x; 1.0599x over previous
#include <cuda_runtime.h>
#include <cuda_fp16.h>
#include <math.h>
#include <stdint.h>

// Problem dims: n = 8192 sequences, V=25 tokens, D=256, H=8, HD=32
#define NSEQ  8192
#define M_TOT 204800        // 8192*25, divisible by 128 -> 1600 M-tiles

// ---------------- device scratch (allocation-free: __device__ globals) -------
__device__ __half g_a[(size_t)M_TOT * 256];     // activations (fp16)
__device__ __half g_qkv[(size_t)M_TOT * 768];   // qkv out (fp16)
__device__ __half g_h[(size_t)M_TOT * 1024];    // ffn hidden (fp16)
// transposed weights: [qkv 768x256 | proj 256x256 | ffn1 1024x256 | ffn2 256x1024]
#define WOFF_QKV  0
#define WOFF_PROJ 196608
#define WOFF_F1   262144
#define WOFF_F2   524288
__device__ __half g_w[786432];

// ---------------- PTX helpers ------------------------------------------------
__device__ __forceinline__ uint32_t smem_u32(const void* p) {
    uint32_t a;
    asm("{ .reg .u64 t; cvta.to.shared.u64 t, %1; cvt.u32.u64 %0, t; }" : "=r"(a) : "l"(p));
    return a;
}
#define CP_COMMIT() asm volatile("cp.async.commit_group;" ::: "memory")
#define CP_WAIT1()  asm volatile("cp.async.wait_group 1;" ::: "memory")
__device__ __forceinline__ void cpa16(uint32_t dst, const void* src) {
    asm volatile("cp.async.cg.shared.global [%0], [%1], 16;" :: "r"(dst), "l"(src));
}
__device__ __forceinline__ void ldm_x4(uint32_t& r0, uint32_t& r1, uint32_t& r2, uint32_t& r3, uint32_t addr) {
    asm volatile("ldmatrix.sync.aligned.m8n8.x4.shared.b16 {%0,%1,%2,%3}, [%4];"
                 : "=r"(r0), "=r"(r1), "=r"(r2), "=r"(r3) : "r"(addr));
}
__device__ __forceinline__ void ldm_x4_t(uint32_t& r0, uint32_t& r1, uint32_t& r2, uint32_t& r3, uint32_t addr) {
    asm volatile("ldmatrix.sync.aligned.m8n8.x4.trans.shared.b16 {%0,%1,%2,%3}, [%4];"
                 : "=r"(r0), "=r"(r1), "=r"(r2), "=r"(r3) : "r"(addr));
}
__device__ __forceinline__ void mma_fp16(float* d, const uint32_t* a, uint32_t b0, uint32_t b1) {
    asm volatile("mma.sync.aligned.m16n8k16.row.col.f32.f16.f16.f32 "
                 "{%0,%1,%2,%3},{%4,%5,%6,%7},{%8,%9},{%0,%1,%2,%3};"
                 : "+f"(d[0]), "+f"(d[1]), "+f"(d[2]), "+f"(d[3])
                 : "r"(a[0]), "r"(a[1]), "r"(a[2]), "r"(a[3]), "r"(b0), "r"(b1));
}
__device__ __forceinline__ float warp_sum(float v) {
#pragma unroll
    for (int o = 16; o > 0; o >>= 1) v += __shfl_xor_sync(0xffffffffu, v, o);
    return v;
}
__device__ __forceinline__ float hsq(uint32_t u) {   // sum of squares of packed half2
    float2 f = __half22float2(*(__half2*)&u);
    return f.x * f.x + f.y * f.y;
}

// ---------------- weight prep: transpose to [N x K] fp16 ---------------------
__global__ void prep_w_kernel(const float* __restrict__ qkvw, const float* __restrict__ projw,
                              const float* __restrict__ f1w, const float* __restrict__ f2w) {
    int idx = blockIdx.x * 256 + threadIdx.x;
    if (idx >= 786432) return;
    const float* src; int K, N, local;
    if (idx < WOFF_PROJ)    { src = qkvw;  K = 256;  N = 768;  local = idx; }
    else if (idx < WOFF_F1) { src = projw; K = 256;  N = 256;  local = idx - WOFF_PROJ; }
    else if (idx < WOFF_F2) { src = f1w;   K = 256;  N = 1024; local = idx - WOFF_F1; }
    else                    { src = f2w;   K = 1024; N = 256;  local = idx - WOFF_F2; }
    int n = local / K, k = local % K;
    g_w[idx] = __float2half_rn(src[(size_t)k * N + n]);
}

// ---------------- LayerNorm -> fp16: one warp per row, float4 ----------------
__global__ void __launch_bounds__(256) ln_h_kernel(
    const float* __restrict__ in, const float* __restrict__ g, const float* __restrict__ b) {
    int row = blockIdx.x * 8 + (threadIdx.x >> 5);
    int lane = threadIdx.x & 31;
    const float4* rp4 = (const float4*)(in + (size_t)row * 256);
    float4 xv[2];
    xv[0] = rp4[lane]; xv[1] = rp4[lane + 32];
    float s1 = xv[0].x + xv[0].y + xv[0].z + xv[0].w + xv[1].x + xv[1].y + xv[1].z + xv[1].w;
    float s2 = xv[0].x*xv[0].x + xv[0].y*xv[0].y + xv[0].z*xv[0].z + xv[0].w*xv[0].w
             + xv[1].x*xv[1].x + xv[1].y*xv[1].y + xv[1].z*xv[1].z + xv[1].w*xv[1].w;
    s1 = warp_sum(s1); s2 = warp_sum(s2);
    float mean = s1 * (1.f / 256.f);
    float var = s2 * (1.f / 256.f) - mean * mean;
    float rs = rsqrtf(var + 1e-5f);
    __half* op = g_a + (size_t)row * 256;
#pragma unroll
    for (int u = 0; u < 2; u++) {
        int c4 = lane + 32 * u;
        float4 gg = ((const float4*)g)[c4];
        float4 bb = ((const float4*)b)[c4];
        float y0 = (xv[u].x - mean) * rs * gg.x + bb.x;
        float y1 = (xv[u].y - mean) * rs * gg.y + bb.y;
        float y2 = (xv[u].z - mean) * rs * gg.z + bb.z;
        float y3 = (xv[u].w - mean) * rs * gg.w + bb.w;
        __half2 h01 = __floats2half2_rn(y0, y1);
        __half2 h23 = __floats2half2_rn(y2, y3);
        *(uint2*)&op[c4 * 4] = make_uint2(*(uint32_t*)&h01, *(uint32_t*)&h23);
    }
}

// ---------------- HMMA fp16 GEMM: C[M_TOT x Ntot] = A @ Wt^T -----------------
// CTA 128x128, warp tile 64x32 (2x4 warps), K-tile 64, 3-stage cp.async,
// single barrier per iteration (load issued before compute).
#define ST_SZ   32768          // per stage: A 16KB + B 16KB
#define GEMM_SMEM (3 * ST_SZ)  // 96KB

__device__ __forceinline__ void load_tile(uint32_t stage_base,
    const __half* __restrict__ A, const __half* __restrict__ B,
    int K, int kk, int m0, int n0, int tid)
{
    uint32_t aB = stage_base;
    uint32_t bB = stage_base + 16384;
#pragma unroll
    for (int i = 0; i < 4; i++) {
        int idx = tid + i * 256;
        int r = idx >> 3, c = idx & 7;                 // row 0..127, 16B chunk 0..7
        uint32_t off = (uint32_t)(r * 128 + c * 16);
        uint32_t sw = off ^ ((uint32_t)(r & 7) << 4);  // SW128
        cpa16(aB + sw, A + (size_t)(m0 + r) * K + kk + c * 8);
    }
#pragma unroll
    for (int i = 0; i < 4; i++) {
        int idx = tid + i * 256;
        int r = idx >> 3, c = idx & 7;
        uint32_t off = (uint32_t)(r * 128 + c * 16);
        uint32_t sw = off ^ ((uint32_t)(r & 7) << 4);
        cpa16(bB + sw, B + (size_t)(n0 + r) * K + kk + c * 8);
    }
}

template<int K, bool GELU, bool HALFOUT, bool RESID>
__global__ void __launch_bounds__(256, 2) gemm_mma(
    const __half* __restrict__ A, int woff,
    const float* __restrict__ bias, int Ntot,
    float* __restrict__ outF, __half* __restrict__ outH,
    const float* __restrict__ resid)
{
    extern __shared__ char smem[];
    uint32_t sb = smem_u32(smem);
    const int tid = threadIdx.x, wid = tid >> 5, lane = tid & 31;
    const int wm = wid & 1, wn = wid >> 1;
    const int m0 = blockIdx.y * 128, n0 = blockIdx.x * 128;
    constexpr int NT = K >> 6;
    const __half* W = g_w + woff;

    float acc[4][4][4];
#pragma unroll
    for (int i = 0; i < 4; i++)
#pragma unroll
        for (int j = 0; j < 4; j++)
#pragma unroll
            for (int kq = 0; kq < 4; kq++) acc[i][j][kq] = 0.f;

    load_tile(sb,         A, W, K, 0,  m0, n0, tid); CP_COMMIT();
    load_tile(sb + ST_SZ, A, W, K, 64, m0, n0, tid); CP_COMMIT();

    const int grp = lane >> 3, lr = lane & 7;
    const int a_row_b = wm * 64 + (grp & 1) * 8 + lr;   // + mf*16
    const int a_kb    = (grp >> 1) * 16;                // bytes
    const int b_row_b = wn * 32 + (grp >> 1) * 8 + lr;  // + np*16
    const int b_kb    = (grp & 1) * 16;                 // bytes

#pragma unroll
    for (int kt = 0; kt < NT; kt++) {
        const int s = kt % 3;
        CP_WAIT1();             // group kt drained (kt+1 may be in flight)
        __syncthreads();        // all warps finished computing kt-1 -> stage (kt+2)%3 reusable
        if (kt + 2 < NT)
            load_tile(sb + ((kt + 2) % 3) * ST_SZ, A, W, K, (kt + 2) * 64, m0, n0, tid);
        CP_COMMIT();

        const uint32_t aBase = sb + s * ST_SZ;
        const uint32_t bBase = aBase + 16384;
#pragma unroll
        for (int ks = 0; ks < 4; ks++) {
            const int kb = ks * 32;
            uint32_t af[4][4];
#pragma unroll
            for (int mf = 0; mf < 4; mf++) {
                int row = a_row_b + mf * 16;
                uint32_t off = (uint32_t)(row * 128 + kb + a_kb);
                uint32_t addr = aBase + (off ^ ((uint32_t)(row & 7) << 4));
                ldm_x4(af[mf][0], af[mf][1], af[mf][2], af[mf][3], addr);
            }
            uint32_t bf[2][4];
#pragma unroll
            for (int np = 0; np < 2; np++) {
                int row = b_row_b + np * 16;
                uint32_t off = (uint32_t)(row * 128 + kb + b_kb);
                uint32_t addr = bBase + (off ^ ((uint32_t)(row & 7) << 4));
                ldm_x4(bf[np][0], bf[np][1], bf[np][2], bf[np][3], addr);
            }
#pragma unroll
            for (int mf = 0; mf < 4; mf++)
#pragma unroll
                for (int nf = 0; nf < 4; nf++)
                    mma_fp16(acc[mf][nf], af[mf], bf[nf >> 1][(nf & 1) * 2], bf[nf >> 1][(nf & 1) * 2 + 1]);
        }
    }

    const int qr = lane >> 2;
    const int qc = (lane & 3) * 2;
#pragma unroll
    for (int mf = 0; mf < 4; mf++) {
#pragma unroll
        for (int nf = 0; nf < 4; nf++) {
            int C = n0 + wn * 32 + nf * 8 + qc;
            float b0 = __ldg(&bias[C]), b1 = __ldg(&bias[C + 1]);
#pragma unroll
            for (int half_ = 0; half_ < 2; half_++) {
                int R = m0 + wm * 64 + mf * 16 + qr + half_ * 8;
                float v0 = acc[mf][nf][half_ * 2 + 0] + b0;
                float v1 = acc[mf][nf][half_ * 2 + 1] + b1;
                if (GELU) {
                    const float is2 = 0.70710678118654752f;
                    v0 = 0.5f * v0 * (1.0f + erff(v0 * is2));
                    v1 = 0.5f * v1 * (1.0f + erff(v1 * is2));
                }
                size_t gidx = (size_t)R * Ntot + C;
                if (RESID) {
                    float2 rv = *(const float2*)&resid[gidx];
                    v0 += rv.x; v1 += rv.y;
                }
                if (HALFOUT) {
                    *(__half2*)&outH[gidx] = __floats2half2_rn(v0, v1);
                } else {
                    *(float2*)&outF[gidx] = make_float2(v0, v1);
                }
            }
        }
    }
}

// ---------------- tensor-core attention: CTA per sequence, warp = head -------
#define ATTN_SMEM 49152   // 8 heads * 3 * 32x32 fp16 (2KB each)
__device__ __forceinline__ uint32_t swz(int row, int byte_) {
    return (uint32_t)((row * 64 + byte_) ^ ((row & 3) << 4));
}
__global__ void __launch_bounds__(256, 2) attn_kernel(const float* __restrict__ logit_scale) {
    extern __shared__ char smem[];
    uint32_t sb = smem_u32(smem);
    const int tid = threadIdx.x, hd = tid >> 5, lane = tid & 31;
    const size_t n = blockIdx.x;

#pragma unroll
    for (int i = 0; i < 12; i++) {
        int idx = tid + i * 256;
        int c16 = idx & 3, h = (idx >> 2) & 7, r = (idx >> 5) & 31, w = idx >> 10;
        uint32_t dst = sb + (uint32_t)(h * 3 + w) * 2048 + swz(r, c16 * 16);
        if (r < 25) {
            const __half* src = g_qkv + (n * 25 + r) * 768 + w * 256 + h * 32 + c16 * 8;
            uint4 v = *(const uint4*)src;
            asm volatile("st.shared.v4.b32 [%0], {%1,%2,%3,%4};" :: "r"(dst), "r"(v.x), "r"(v.y), "r"(v.z), "r"(v.w));
        } else {
            asm volatile("st.shared.v4.b32 [%0], {%1,%1,%1,%1};" :: "r"(dst), "r"(0u));
        }
    }
    __syncthreads();

    const uint32_t qb = sb + (uint32_t)hd * 3 * 2048;
    const uint32_t kb = qb + 2048;
    const uint32_t vb = qb + 4096;
    const int grp = lane >> 3, lr = lane & 7;
    const int qr = lane >> 2, qc = lane & 3;

    uint32_t af[2][2][4];
#pragma unroll
    for (int mf = 0; mf < 2; mf++)
#pragma unroll
        for (int ks = 0; ks < 2; ks++) {
            int row = mf * 16 + (grp & 1) * 8 + lr;
            uint32_t addr = qb + swz(row, (grp >> 1) * 16 + ks * 32);
            ldm_x4(af[mf][ks][0], af[mf][ks][1], af[mf][ks][2], af[mf][ks][3], addr);
        }
    uint32_t kf[2][2][4];
#pragma unroll
    for (int np = 0; np < 2; np++)
#pragma unroll
        for (int ks = 0; ks < 2; ks++) {
            int row = np * 16 + (grp >> 1) * 8 + lr;
            uint32_t addr = kb + swz(row, (grp & 1) * 16 + ks * 32);
            ldm_x4(kf[np][ks][0], kf[np][ks][1], kf[np][ks][2], kf[np][ks][3], addr);
        }

    float acc[2][4][4];
#pragma unroll
    for (int mf = 0; mf < 2; mf++)
#pragma unroll
        for (int nf = 0; nf < 4; nf++)
#pragma unroll
            for (int u = 0; u < 4; u++) acc[mf][nf][u] = 0.f;
#pragma unroll
    for (int ks = 0; ks < 2; ks++)
#pragma unroll
        for (int mf = 0; mf < 2; mf++)
#pragma unroll
            for (int nf = 0; nf < 4; nf++)
                mma_fp16(acc[mf][nf], af[mf][ks], kf[nf >> 1][ks][(nf & 1) * 2], kf[nf >> 1][ks][(nf & 1) * 2 + 1]);

    const float LOG100 = 4.6051701859880914f;
    const float stot = __expf(fminf(__ldg(&logit_scale[hd]), LOG100)) * 0.17677669529663687f;

    float nqp[4], nkp[4];
#pragma unroll
    for (int i = 0; i < 4; i++) {
        int mf = i >> 1, h2 = i & 1;
        nqp[i] = hsq(af[mf][0][h2]) + hsq(af[mf][0][h2 + 2]) + hsq(af[mf][1][h2]) + hsq(af[mf][1][h2 + 2]);
    }
#pragma unroll
    for (int i = 0; i < 4; i++) {
        int np = i >> 1, t = i & 1;
        nkp[i] = hsq(kf[np][0][2 * t]) + hsq(kf[np][0][2 * t + 1]) + hsq(kf[np][1][2 * t]) + hsq(kf[np][1][2 * t + 1]);
    }
#pragma unroll
    for (int o = 1; o <= 2; o <<= 1) {
#pragma unroll
        for (int i = 0; i < 4; i++) {
            nqp[i] += __shfl_xor_sync(0xffffffffu, nqp[i], o);
            nkp[i] += __shfl_xor_sync(0xffffffffu, nkp[i], o);
        }
    }
    float nqr4[4], nkr4[4];
#pragma unroll
    for (int i = 0; i < 4; i++) {
        nqr4[i] = stot / fmaxf(sqrtf(nqp[i]), 1e-12f);
        nkr4[i] = 1.0f / fmaxf(sqrtf(nkp[i]), 1e-12f);
    }
    float skc[4][2];
#pragma unroll
    for (int nf = 0; nf < 4; nf++)
#pragma unroll
        for (int u = 0; u < 2; u++)
            skc[nf][u] = __shfl_sync(0xffffffffu, nkr4[nf], ((2 * qc + u) & 7) << 2);

#pragma unroll
    for (int mf = 0; mf < 2; mf++)
#pragma unroll
        for (int h2 = 0; h2 < 2; h2++) {
            float sq_ = nqr4[mf * 2 + h2];
            float vals[8];
#pragma unroll
            for (int nf = 0; nf < 4; nf++)
#pragma unroll
                for (int u = 0; u < 2; u++) {
                    float v = acc[mf][nf][h2 * 2 + u] * sq_ * skc[nf][u];
                    if (nf == 3 && (24 + 2 * qc + u) >= 25) v = -1e30f;
                    vals[nf * 2 + u] = v;
                }
            float m = vals[0];
#pragma unroll
            for (int j = 1; j < 8; j++) m = fmaxf(m, vals[j]);
            m = fmaxf(m, __shfl_xor_sync(0xffffffffu, m, 1));
            m = fmaxf(m, __shfl_xor_sync(0xffffffffu, m, 2));
            float s = 0.f;
#pragma unroll
            for (int j = 0; j < 8; j++) { vals[j] = __expf(vals[j] - m); s += vals[j]; }
            s += __shfl_xor_sync(0xffffffffu, s, 1);
            s += __shfl_xor_sync(0xffffffffu, s, 2);
            float inv = 1.0f / s;
#pragma unroll
            for (int nf = 0; nf < 4; nf++)
#pragma unroll
                for (int u = 0; u < 2; u++)
                    acc[mf][nf][h2 * 2 + u] = vals[nf * 2 + u] * inv;
        }

    uint32_t pa[2][2][4];
#pragma unroll
    for (int mf = 0; mf < 2; mf++)
#pragma unroll
        for (int ks = 0; ks < 2; ks++) {
            __half2 h0 = __floats2half2_rn(acc[mf][2 * ks][0], acc[mf][2 * ks][1]);
            __half2 h1 = __floats2half2_rn(acc[mf][2 * ks][2], acc[mf][2 * ks][3]);
            __half2 h2_ = __floats2half2_rn(acc[mf][2 * ks + 1][0], acc[mf][2 * ks + 1][1]);
            __half2 h3 = __floats2half2_rn(acc[mf][2 * ks + 1][2], acc[mf][2 * ks + 1][3]);
            pa[mf][ks][0] = *(uint32_t*)&h0; pa[mf][ks][1] = *(uint32_t*)&h1;
            pa[mf][ks][2] = *(uint32_t*)&h2_; pa[mf][ks][3] = *(uint32_t*)&h3;
        }

    uint32_t vf[2][2][4];
#pragma unroll
    for (int ks = 0; ks < 2; ks++)
#pragma unroll
        for (int np = 0; np < 2; np++) {
            int row = ks * 16 + (grp & 1) * 8 + lr;
            uint32_t addr = vb + swz(row, (grp >> 1) * 16 + np * 32);
            ldm_x4_t(vf[ks][np][0], vf[ks][np][1], vf[ks][np][2], vf[ks][np][3], addr);
        }

    float oacc[2][4][4];
#pragma unroll
    for (int mf = 0; mf < 2; mf++)
#pragma unroll
        for (int nf = 0; nf < 4; nf++)
#pragma unroll
            for (int u = 0; u < 4; u++) oacc[mf][nf][u] = 0.f;
#pragma unroll
    for (int ks = 0; ks < 2; ks++)
#pragma unroll
        for (int mf = 0; mf < 2; mf++)
#pragma unroll
            for (int nf = 0; nf < 4; nf++)
                mma_fp16(oacc[mf][nf], pa[mf][ks], vf[ks][nf >> 1][(nf & 1) * 2], vf[ks][nf >> 1][(nf & 1) * 2 + 1]);

#pragma unroll
    for (int mf = 0; mf < 2; mf++)
#pragma unroll
        for (int h2 = 0; h2 < 2; h2++) {
            int R = mf * 16 + h2 * 8 + qr;
            if (R < 25) {
#pragma unroll
                for (int nf = 0; nf < 4; nf++) {
                    int d = nf * 8 + 2 * qc;
                    __half2 hv = __floats2half2_rn(oacc[mf][nf][h2 * 2], oacc[mf][nf][h2 * 2 + 1]);
                    *(__half2*)&g_a[(n * 25 + R) * 256 + hd * 32 + d] = hv;
                }
            }
        }
}

// ---------------- launch -----------------------------------------------------
extern "C" void kernel_launch(void* const* d_in, const int* in_sizes, int n_in,
                              void* d_out, int out_size)
{
    const float* x           = (const float*)d_in[0];
    const float* ln1_g       = (const float*)d_in[1];
    const float* ln1_b       = (const float*)d_in[2];
    const float* qkv_w       = (const float*)d_in[3];
    const float* qkv_b       = (const float*)d_in[4];
    const float* proj_w      = (const float*)d_in[5];
    const float* proj_b      = (const float*)d_in[6];
    const float* logit_scale = (const float*)d_in[7];
    const float* ln2_g       = (const float*)d_in[8];
    const float* ln2_b       = (const float*)d_in[9];
    const float* ffn_w1      = (const float*)d_in[10];
    const float* ffn_b1      = (const float*)d_in[11];
    const float* ffn_w2      = (const float*)d_in[12];
    const float* ffn_b2      = (const float*)d_in[13];
    float* out = (float*)d_out;

    cudaFuncSetAttribute(gemm_mma<256 ,false,true ,false>, cudaFuncAttributeMaxDynamicSharedMemorySize, GEMM_SMEM);
    cudaFuncSetAttribute(gemm_mma<256 ,false,false,true >, cudaFuncAttributeMaxDynamicSharedMemorySize, GEMM_SMEM);
    cudaFuncSetAttribute(gemm_mma<256 ,true ,true ,false>, cudaFuncAttributeMaxDynamicSharedMemorySize, GEMM_SMEM);
    cudaFuncSetAttribute(gemm_mma<1024,false,false,true >, cudaFuncAttributeMaxDynamicSharedMemorySize, GEMM_SMEM);
    cudaFuncSetAttribute(attn_kernel, cudaFuncAttributeMaxDynamicSharedMemorySize, ATTN_SMEM);

    __half *ap, *qkvp, *hp;
    cudaGetSymbolAddress((void**)&ap,   g_a);
    cudaGetSymbolAddress((void**)&qkvp, g_qkv);
    cudaGetSymbolAddress((void**)&hp,   g_h);

    // 1) weight transpose -> fp16
    prep_w_kernel<<<3072, 256>>>(qkv_w, proj_w, ffn_w1, ffn_w2);
    // 2) LN1 -> fp16 activations
    ln_h_kernel<<<M_TOT / 8, 256>>>(x, ln1_g, ln1_b);
    // 3) QKV GEMM -> g_qkv (fp16)
    gemm_mma<256,false,true,false><<<dim3(6, 1600), 256, GEMM_SMEM>>>(
        ap, WOFF_QKV, qkv_b, 768, nullptr, qkvp, nullptr);
    // 4) attention -> g_a (fp16)
    attn_kernel<<<NSEQ, 256, ATTN_SMEM>>>(logit_scale);
    // 5) proj GEMM + residual(x) -> d_out (fp32)
    gemm_mma<256,false,false,true><<<dim3(2, 1600), 256, GEMM_SMEM>>>(
        ap, WOFF_PROJ, proj_b, 256, out, nullptr, x);
    // 6) LN2 -> fp16 activations
    ln_h_kernel<<<M_TOT / 8, 256>>>(out, ln2_g, ln2_b);
    // 7) FFN1 GEMM + GELU -> g_h (fp16)
    gemm_mma<256,true,true,false><<<dim3(8, 1600), 256, GEMM_SMEM>>>(
        ap, WOFF_F1, ffn_b1, 1024, nullptr, hp, nullptr);
    // 8) FFN2 GEMM + residual -> d_out (final)
    gemm_mma<1024,false,false,true><<<dim3(2, 1600), 256, GEMM_SMEM>>>(
        hp, WOFF_F2, ffn_b2, 256, out, nullptr, out);
}

// round 14
// speedup vs baseline: 10.9214x; 1.0272x over previous
#include <cuda_runtime.h>
#include <cuda_fp16.h>
#include <math.h>
#include <stdint.h>

// Problem dims: n = 8192 sequences, V=25 tokens, D=256, H=8, HD=32
#define NSEQ  8192
#define M_TOT 204800        // 8192*25, divisible by 128 -> 1600 M-tiles

// ---------------- device scratch (allocation-free: __device__ globals) -------
__device__ __half g_a[(size_t)M_TOT * 256];     // activations (fp16)
__device__ __half g_qkv[(size_t)M_TOT * 768];   // qkv out (fp16)
__device__ __half g_h[(size_t)M_TOT * 1024];    // ffn hidden (fp16)
// transposed weights: [qkv 768x256 | proj 256x256 | ffn1 1024x256 | ffn2 256x1024]
#define WOFF_QKV  0
#define WOFF_PROJ 196608
#define WOFF_F1   262144
#define WOFF_F2   524288
__device__ __half g_w[786432];

// ---------------- PTX helpers ------------------------------------------------
__device__ __forceinline__ uint32_t smem_u32(const void* p) {
    uint32_t a;
    asm("{ .reg .u64 t; cvta.to.shared.u64 t, %1; cvt.u32.u64 %0, t; }" : "=r"(a) : "l"(p));
    return a;
}
#define CP_COMMIT() asm volatile("cp.async.commit_group;" ::: "memory")
#define CP_WAIT1()  asm volatile("cp.async.wait_group 1;" ::: "memory")
__device__ __forceinline__ void cpa16(uint32_t dst, const void* src) {
    asm volatile("cp.async.cg.shared.global [%0], [%1], 16;" :: "r"(dst), "l"(src));
}
__device__ __forceinline__ void ldm_x4(uint32_t& r0, uint32_t& r1, uint32_t& r2, uint32_t& r3, uint32_t addr) {
    asm volatile("ldmatrix.sync.aligned.m8n8.x4.shared.b16 {%0,%1,%2,%3}, [%4];"
                 : "=r"(r0), "=r"(r1), "=r"(r2), "=r"(r3) : "r"(addr));
}
__device__ __forceinline__ void ldm_x4_t(uint32_t& r0, uint32_t& r1, uint32_t& r2, uint32_t& r3, uint32_t addr) {
    asm volatile("ldmatrix.sync.aligned.m8n8.x4.trans.shared.b16 {%0,%1,%2,%3}, [%4];"
                 : "=r"(r0), "=r"(r1), "=r"(r2), "=r"(r3) : "r"(addr));
}
__device__ __forceinline__ void mma_fp16(float* d, const uint32_t* a, uint32_t b0, uint32_t b1) {
    asm volatile("mma.sync.aligned.m16n8k16.row.col.f32.f16.f16.f32 "
                 "{%0,%1,%2,%3},{%4,%5,%6,%7},{%8,%9},{%0,%1,%2,%3};"
                 : "+f"(d[0]), "+f"(d[1]), "+f"(d[2]), "+f"(d[3])
                 : "r"(a[0]), "r"(a[1]), "r"(a[2]), "r"(a[3]), "r"(b0), "r"(b1));
}
__device__ __forceinline__ float warp_sum(float v) {
#pragma unroll
    for (int o = 16; o > 0; o >>= 1) v += __shfl_xor_sync(0xffffffffu, v, o);
    return v;
}
__device__ __forceinline__ float hsq(uint32_t u) {   // sum of squares of packed half2
    float2 f = __half22float2(*(__half2*)&u);
    return f.x * f.x + f.y * f.y;
}

// ---------------- weight prep: transpose to [N x K] fp16 ---------------------
__global__ void prep_w_kernel(const float* __restrict__ qkvw, const float* __restrict__ projw,
                              const float* __restrict__ f1w, const float* __restrict__ f2w) {
    int idx = blockIdx.x * 256 + threadIdx.x;
    if (idx >= 786432) return;
    const float* src; int K, N, local;
    if (idx < WOFF_PROJ)    { src = qkvw;  K = 256;  N = 768;  local = idx; }
    else if (idx < WOFF_F1) { src = projw; K = 256;  N = 256;  local = idx - WOFF_PROJ; }
    else if (idx < WOFF_F2) { src = f1w;   K = 256;  N = 1024; local = idx - WOFF_F1; }
    else                    { src = f2w;   K = 1024; N = 256;  local = idx - WOFF_F2; }
    int n = local / K, k = local % K;
    g_w[idx] = __float2half_rn(src[(size_t)k * N + n]);
}

// ---------------- LayerNorm -> fp16: one warp per row, float4 ----------------
__global__ void __launch_bounds__(256) ln_h_kernel(
    const float* __restrict__ in, const float* __restrict__ g, const float* __restrict__ b) {
    int row = blockIdx.x * 8 + (threadIdx.x >> 5);
    int lane = threadIdx.x & 31;
    const float4* rp4 = (const float4*)(in + (size_t)row * 256);
    float4 xv[2];
    xv[0] = rp4[lane]; xv[1] = rp4[lane + 32];
    float s1 = xv[0].x + xv[0].y + xv[0].z + xv[0].w + xv[1].x + xv[1].y + xv[1].z + xv[1].w;
    float s2 = xv[0].x*xv[0].x + xv[0].y*xv[0].y + xv[0].z*xv[0].z + xv[0].w*xv[0].w
             + xv[1].x*xv[1].x + xv[1].y*xv[1].y + xv[1].z*xv[1].z + xv[1].w*xv[1].w;
    s1 = warp_sum(s1); s2 = warp_sum(s2);
    float mean = s1 * (1.f / 256.f);
    float var = s2 * (1.f / 256.f) - mean * mean;
    float rs = rsqrtf(var + 1e-5f);
    __half* op = g_a + (size_t)row * 256;
#pragma unroll
    for (int u = 0; u < 2; u++) {
        int c4 = lane + 32 * u;
        float4 gg = ((const float4*)g)[c4];
        float4 bb = ((const float4*)b)[c4];
        float y0 = (xv[u].x - mean) * rs * gg.x + bb.x;
        float y1 = (xv[u].y - mean) * rs * gg.y + bb.y;
        float y2 = (xv[u].z - mean) * rs * gg.z + bb.z;
        float y3 = (xv[u].w - mean) * rs * gg.w + bb.w;
        __half2 h01 = __floats2half2_rn(y0, y1);
        __half2 h23 = __floats2half2_rn(y2, y3);
        *(uint2*)&op[c4 * 4] = make_uint2(*(uint32_t*)&h01, *(uint32_t*)&h23);
    }
}

// ---------------- HMMA fp16 GEMM: C[M_TOT x Ntot] = A @ Wt^T -----------------
// CTA 128x128, 4 warps as 2x2, warp tile 64x64 (reduces LDSM duplication),
// K-tile 64, 3-stage cp.async, single barrier per iteration.
#define ST_SZ   32768          // per stage: A 16KB + B 16KB
#define GEMM_SMEM (3 * ST_SZ)  // 96KB

__device__ __forceinline__ void load_tile(uint32_t stage_base,
    const __half* __restrict__ A, const __half* __restrict__ B,
    int K, int kk, int m0, int n0, int tid)
{
    uint32_t aB = stage_base;
    uint32_t bB = stage_base + 16384;
#pragma unroll
    for (int i = 0; i < 8; i++) {
        int idx = tid + i * 128;
        int r = idx >> 3, c = idx & 7;                 // row 0..127, 16B chunk 0..7
        uint32_t off = (uint32_t)(r * 128 + c * 16);
        uint32_t sw = off ^ ((uint32_t)(r & 7) << 4);  // SW128
        cpa16(aB + sw, A + (size_t)(m0 + r) * K + kk + c * 8);
    }
#pragma unroll
    for (int i = 0; i < 8; i++) {
        int idx = tid + i * 128;
        int r = idx >> 3, c = idx & 7;
        uint32_t off = (uint32_t)(r * 128 + c * 16);
        uint32_t sw = off ^ ((uint32_t)(r & 7) << 4);
        cpa16(bB + sw, B + (size_t)(n0 + r) * K + kk + c * 8);
    }
}

template<int K, bool GELU, bool HALFOUT, bool RESID>
__global__ void __launch_bounds__(128, 2) gemm_mma(
    const __half* __restrict__ A, int woff,
    const float* __restrict__ bias, int Ntot,
    float* __restrict__ outF, __half* __restrict__ outH,
    const float* __restrict__ resid)
{
    extern __shared__ char smem[];
    uint32_t sb = smem_u32(smem);
    const int tid = threadIdx.x, wid = tid >> 5, lane = tid & 31;
    const int wm = wid & 1, wn = wid >> 1;          // 2x2 warp grid
    const int m0 = blockIdx.y * 128, n0 = blockIdx.x * 128;
    constexpr int NT = K >> 6;
    const __half* W = g_w + woff;

    float acc[4][8][4];
#pragma unroll
    for (int i = 0; i < 4; i++)
#pragma unroll
        for (int j = 0; j < 8; j++)
#pragma unroll
            for (int kq = 0; kq < 4; kq++) acc[i][j][kq] = 0.f;

    load_tile(sb,         A, W, K, 0,  m0, n0, tid); CP_COMMIT();
    load_tile(sb + ST_SZ, A, W, K, 64, m0, n0, tid); CP_COMMIT();

    const int grp = lane >> 3, lr = lane & 7;
    const int a_row_b = wm * 64 + (grp & 1) * 8 + lr;   // + mf*16
    const int a_kb    = (grp >> 1) * 16;                // bytes
    const int b_row_b = wn * 64 + (grp >> 1) * 8 + lr;  // + np*16
    const int b_kb    = (grp & 1) * 16;                 // bytes

#pragma unroll
    for (int kt = 0; kt < NT; kt++) {
        const int s = kt % 3;
        CP_WAIT1();             // group kt drained
        __syncthreads();        // stage (kt+2)%3 reusable
        if (kt + 2 < NT)
            load_tile(sb + ((kt + 2) % 3) * ST_SZ, A, W, K, (kt + 2) * 64, m0, n0, tid);
        CP_COMMIT();

        const uint32_t aBase = sb + s * ST_SZ;
        const uint32_t bBase = aBase + 16384;
#pragma unroll
        for (int ks = 0; ks < 4; ks++) {
            const int kb = ks * 32;
            uint32_t af[4][4];
#pragma unroll
            for (int mf = 0; mf < 4; mf++) {
                int row = a_row_b + mf * 16;
                uint32_t off = (uint32_t)(row * 128 + kb + a_kb);
                uint32_t addr = aBase + (off ^ ((uint32_t)(row & 7) << 4));
                ldm_x4(af[mf][0], af[mf][1], af[mf][2], af[mf][3], addr);
            }
            uint32_t bf[4][4];
#pragma unroll
            for (int np = 0; np < 4; np++) {
                int row = b_row_b + np * 16;
                uint32_t off = (uint32_t)(row * 128 + kb + b_kb);
                uint32_t addr = bBase + (off ^ ((uint32_t)(row & 7) << 4));
                ldm_x4(bf[np][0], bf[np][1], bf[np][2], bf[np][3], addr);
            }
#pragma unroll
            for (int mf = 0; mf < 4; mf++)
#pragma unroll
                for (int nf = 0; nf < 8; nf++)
                    mma_fp16(acc[mf][nf], af[mf], bf[nf >> 1][(nf & 1) * 2], bf[nf >> 1][(nf & 1) * 2 + 1]);
        }
    }

    const int qr = lane >> 2;
    const int qc = (lane & 3) * 2;
#pragma unroll
    for (int mf = 0; mf < 4; mf++) {
#pragma unroll
        for (int nf = 0; nf < 8; nf++) {
            int C = n0 + wn * 64 + nf * 8 + qc;
            float b0 = __ldg(&bias[C]), b1 = __ldg(&bias[C + 1]);
#pragma unroll
            for (int half_ = 0; half_ < 2; half_++) {
                int R = m0 + wm * 64 + mf * 16 + qr + half_ * 8;
                float v0 = acc[mf][nf][half_ * 2 + 0] + b0;
                float v1 = acc[mf][nf][half_ * 2 + 1] + b1;
                if (GELU) {
                    const float is2 = 0.70710678118654752f;
                    v0 = 0.5f * v0 * (1.0f + erff(v0 * is2));
                    v1 = 0.5f * v1 * (1.0f + erff(v1 * is2));
                }
                size_t gidx = (size_t)R * Ntot + C;
                if (RESID) {
                    float2 rv = *(const float2*)&resid[gidx];
                    v0 += rv.x; v1 += rv.y;
                }
                if (HALFOUT) {
                    *(__half2*)&outH[gidx] = __floats2half2_rn(v0, v1);
                } else {
                    *(float2*)&outF[gidx] = make_float2(v0, v1);
                }
            }
        }
    }
}

// ---------------- tensor-core attention: CTA per sequence, warp = head -------
#define ATTN_SMEM 49152   // 8 heads * 3 * 32x32 fp16 (2KB each)
__device__ __forceinline__ uint32_t swz(int row, int byte_) {
    return (uint32_t)((row * 64 + byte_) ^ ((row & 3) << 4));
}
__global__ void __launch_bounds__(256, 2) attn_kernel(const float* __restrict__ logit_scale) {
    extern __shared__ char smem[];
    uint32_t sb = smem_u32(smem);
    const int tid = threadIdx.x, hd = tid >> 5, lane = tid & 31;
    const size_t n = blockIdx.x;

#pragma unroll
    for (int i = 0; i < 12; i++) {
        int idx = tid + i * 256;
        int c16 = idx & 3, h = (idx >> 2) & 7, r = (idx >> 5) & 31, w = idx >> 10;
        uint32_t dst = sb + (uint32_t)(h * 3 + w) * 2048 + swz(r, c16 * 16);
        if (r < 25) {
            const __half* src = g_qkv + (n * 25 + r) * 768 + w * 256 + h * 32 + c16 * 8;
            uint4 v = *(const uint4*)src;
            asm volatile("st.shared.v4.b32 [%0], {%1,%2,%3,%4};" :: "r"(dst), "r"(v.x), "r"(v.y), "r"(v.z), "r"(v.w));
        } else {
            asm volatile("st.shared.v4.b32 [%0], {%1,%1,%1,%1};" :: "r"(dst), "r"(0u));
        }
    }
    __syncthreads();

    const uint32_t qb = sb + (uint32_t)hd * 3 * 2048;
    const uint32_t kb = qb + 2048;
    const uint32_t vb = qb + 4096;
    const int grp = lane >> 3, lr = lane & 7;
    const int qr = lane >> 2, qc = lane & 3;

    uint32_t af[2][2][4];
#pragma unroll
    for (int mf = 0; mf < 2; mf++)
#pragma unroll
        for (int ks = 0; ks < 2; ks++) {
            int row = mf * 16 + (grp & 1) * 8 + lr;
            uint32_t addr = qb + swz(row, (grp >> 1) * 16 + ks * 32);
            ldm_x4(af[mf][ks][0], af[mf][ks][1], af[mf][ks][2], af[mf][ks][3], addr);
        }
    uint32_t kf[2][2][4];
#pragma unroll
    for (int np = 0; np < 2; np++)
#pragma unroll
        for (int ks = 0; ks < 2; ks++) {
            int row = np * 16 + (grp >> 1) * 8 + lr;
            uint32_t addr = kb + swz(row, (grp & 1) * 16 + ks * 32);
            ldm_x4(kf[np][ks][0], kf[np][ks][1], kf[np][ks][2], kf[np][ks][3], addr);
        }

    float acc[2][4][4];
#pragma unroll
    for (int mf = 0; mf < 2; mf++)
#pragma unroll
        for (int nf = 0; nf < 4; nf++)
#pragma unroll
            for (int u = 0; u < 4; u++) acc[mf][nf][u] = 0.f;
#pragma unroll
    for (int ks = 0; ks < 2; ks++)
#pragma unroll
        for (int mf = 0; mf < 2; mf++)
#pragma unroll
            for (int nf = 0; nf < 4; nf++)
                mma_fp16(acc[mf][nf], af[mf][ks], kf[nf >> 1][ks][(nf & 1) * 2], kf[nf >> 1][ks][(nf & 1) * 2 + 1]);

    const float LOG100 = 4.6051701859880914f;
    const float stot = __expf(fminf(__ldg(&logit_scale[hd]), LOG100)) * 0.17677669529663687f;

    float nqp[4], nkp[4];
#pragma unroll
    for (int i = 0; i < 4; i++) {
        int mf = i >> 1, h2 = i & 1;
        nqp[i] = hsq(af[mf][0][h2]) + hsq(af[mf][0][h2 + 2]) + hsq(af[mf][1][h2]) + hsq(af[mf][1][h2 + 2]);
    }
#pragma unroll
    for (int i = 0; i < 4; i++) {
        int np = i >> 1, t = i & 1;
        nkp[i] = hsq(kf[np][0][2 * t]) + hsq(kf[np][0][2 * t + 1]) + hsq(kf[np][1][2 * t]) + hsq(kf[np][1][2 * t + 1]);
    }
#pragma unroll
    for (int o = 1; o <= 2; o <<= 1) {
#pragma unroll
        for (int i = 0; i < 4; i++) {
            nqp[i] += __shfl_xor_sync(0xffffffffu, nqp[i], o);
            nkp[i] += __shfl_xor_sync(0xffffffffu, nkp[i], o);
        }
    }
    float nqr4[4], nkr4[4];
#pragma unroll
    for (int i = 0; i < 4; i++) {
        nqr4[i] = stot / fmaxf(sqrtf(nqp[i]), 1e-12f);
        nkr4[i] = 1.0f / fmaxf(sqrtf(nkp[i]), 1e-12f);
    }
    float skc[4][2];
#pragma unroll
    for (int nf = 0; nf < 4; nf++)
#pragma unroll
        for (int u = 0; u < 2; u++)
            skc[nf][u] = __shfl_sync(0xffffffffu, nkr4[nf], ((2 * qc + u) & 7) << 2);

#pragma unroll
    for (int mf = 0; mf < 2; mf++)
#pragma unroll
        for (int h2 = 0; h2 < 2; h2++) {
            float sq_ = nqr4[mf * 2 + h2];
            float vals[8];
#pragma unroll
            for (int nf = 0; nf < 4; nf++)
#pragma unroll
                for (int u = 0; u < 2; u++) {
                    float v = acc[mf][nf][h2 * 2 + u] * sq_ * skc[nf][u];
                    if (nf == 3 && (24 + 2 * qc + u) >= 25) v = -1e30f;
                    vals[nf * 2 + u] = v;
                }
            float m = vals[0];
#pragma unroll
            for (int j = 1; j < 8; j++) m = fmaxf(m, vals[j]);
            m = fmaxf(m, __shfl_xor_sync(0xffffffffu, m, 1));
            m = fmaxf(m, __shfl_xor_sync(0xffffffffu, m, 2));
            float s = 0.f;
#pragma unroll
            for (int j = 0; j < 8; j++) { vals[j] = __expf(vals[j] - m); s += vals[j]; }
            s += __shfl_xor_sync(0xffffffffu, s, 1);
            s += __shfl_xor_sync(0xffffffffu, s, 2);
            float inv = 1.0f / s;
#pragma unroll
            for (int nf = 0; nf < 4; nf++)
#pragma unroll
                for (int u = 0; u < 2; u++)
                    acc[mf][nf][h2 * 2 + u] = vals[nf * 2 + u] * inv;
        }

    uint32_t pa[2][2][4];
#pragma unroll
    for (int mf = 0; mf < 2; mf++)
#pragma unroll
        for (int ks = 0; ks < 2; ks++) {
            __half2 h0 = __floats2half2_rn(acc[mf][2 * ks][0], acc[mf][2 * ks][1]);
            __half2 h1 = __floats2half2_rn(acc[mf][2 * ks][2], acc[mf][2 * ks][3]);
            __half2 h2_ = __floats2half2_rn(acc[mf][2 * ks + 1][0], acc[mf][2 * ks + 1][1]);
            __half2 h3 = __floats2half2_rn(acc[mf][2 * ks + 1][2], acc[mf][2 * ks + 1][3]);
            pa[mf][ks][0] = *(uint32_t*)&h0; pa[mf][ks][1] = *(uint32_t*)&h1;
            pa[mf][ks][2] = *(uint32_t*)&h2_; pa[mf][ks][3] = *(uint32_t*)&h3;
        }

    uint32_t vf[2][2][4];
#pragma unroll
    for (int ks = 0; ks < 2; ks++)
#pragma unroll
        for (int np = 0; np < 2; np++) {
            int row = ks * 16 + (grp & 1) * 8 + lr;
            uint32_t addr = vb + swz(row, (grp >> 1) * 16 + np * 32);
            ldm_x4_t(vf[ks][np][0], vf[ks][np][1], vf[ks][np][2], vf[ks][np][3], addr);
        }

    float oacc[2][4][4];
#pragma unroll
    for (int mf = 0; mf < 2; mf++)
#pragma unroll
        for (int nf = 0; nf < 4; nf++)
#pragma unroll
            for (int u = 0; u < 4; u++) oacc[mf][nf][u] = 0.f;
#pragma unroll
    for (int ks = 0; ks < 2; ks++)
#pragma unroll
        for (int mf = 0; mf < 2; mf++)
#pragma unroll
            for (int nf = 0; nf < 4; nf++)
                mma_fp16(oacc[mf][nf], pa[mf][ks], vf[ks][nf >> 1][(nf & 1) * 2], vf[ks][nf >> 1][(nf & 1) * 2 + 1]);

#pragma unroll
    for (int mf = 0; mf < 2; mf++)
#pragma unroll
        for (int h2 = 0; h2 < 2; h2++) {
            int R = mf * 16 + h2 * 8 + qr;
            if (R < 25) {
#pragma unroll
                for (int nf = 0; nf < 4; nf++) {
                    int d = nf * 8 + 2 * qc;
                    __half2 hv = __floats2half2_rn(oacc[mf][nf][h2 * 2], oacc[mf][nf][h2 * 2 + 1]);
                    *(__half2*)&g_a[(n * 25 + R) * 256 + hd * 32 + d] = hv;
                }
            }
        }
}

// ---------------- launch -----------------------------------------------------
extern "C" void kernel_launch(void* const* d_in, const int* in_sizes, int n_in,
                              void* d_out, int out_size)
{
    const float* x           = (const float*)d_in[0];
    const float* ln1_g       = (const float*)d_in[1];
    const float* ln1_b       = (const float*)d_in[2];
    const float* qkv_w       = (const float*)d_in[3];
    const float* qkv_b       = (const float*)d_in[4];
    const float* proj_w      = (const float*)d_in[5];
    const float* proj_b      = (const float*)d_in[6];
    const float* logit_scale = (const float*)d_in[7];
    const float* ln2_g       = (const float*)d_in[8];
    const float* ln2_b       = (const float*)d_in[9];
    const float* ffn_w1      = (const float*)d_in[10];
    const float* ffn_b1      = (const float*)d_in[11];
    const float* ffn_w2      = (const float*)d_in[12];
    const float* ffn_b2      = (const float*)d_in[13];
    float* out = (float*)d_out;

    cudaFuncSetAttribute(gemm_mma<256 ,false,true ,false>, cudaFuncAttributeMaxDynamicSharedMemorySize, GEMM_SMEM);
    cudaFuncSetAttribute(gemm_mma<256 ,false,false,true >, cudaFuncAttributeMaxDynamicSharedMemorySize, GEMM_SMEM);
    cudaFuncSetAttribute(gemm_mma<256 ,true ,true ,false>, cudaFuncAttributeMaxDynamicSharedMemorySize, GEMM_SMEM);
    cudaFuncSetAttribute(gemm_mma<1024,false,false,true >, cudaFuncAttributeMaxDynamicSharedMemorySize, GEMM_SMEM);
    cudaFuncSetAttribute(attn_kernel, cudaFuncAttributeMaxDynamicSharedMemorySize, ATTN_SMEM);

    __half *ap, *qkvp, *hp;
    cudaGetSymbolAddress((void**)&ap,   g_a);
    cudaGetSymbolAddress((void**)&qkvp, g_qkv);
    cudaGetSymbolAddress((void**)&hp,   g_h);

    // 1) weight transpose -> fp16
    prep_w_kernel<<<3072, 256>>>(qkv_w, proj_w, ffn_w1, ffn_w2);
    // 2) LN1 -> fp16 activations
    ln_h_kernel<<<M_TOT / 8, 256>>>(x, ln1_g, ln1_b);
    // 3) QKV GEMM -> g_qkv (fp16)
    gemm_mma<256,false,true,false><<<dim3(6, 1600), 128, GEMM_SMEM>>>(
        ap, WOFF_QKV, qkv_b, 768, nullptr, qkvp, nullptr);
    // 4) attention -> g_a (fp16)
    attn_kernel<<<NSEQ, 256, ATTN_SMEM>>>(logit_scale);
    // 5) proj GEMM + residual(x) -> d_out (fp32)
    gemm_mma<256,false,false,true><<<dim3(2, 1600), 128, GEMM_SMEM>>>(
        ap, WOFF_PROJ, proj_b, 256, out, nullptr, x);
    // 6) LN2 -> fp16 activations
    ln_h_kernel<<<M_TOT / 8, 256>>>(out, ln2_g, ln2_b);
    // 7) FFN1 GEMM + GELU -> g_h (fp16)
    gemm_mma<256,true,true,false><<<dim3(8, 1600), 128, GEMM_SMEM>>>(
        ap, WOFF_F1, ffn_b1, 1024, nullptr, hp, nullptr);
    // 8) FFN2 GEMM + residual -> d_out (final)
    gemm_mma<1024,false,false,true><<<dim3(2, 1600), 128, GEMM_SMEM>>>(
        hp, WOFF_F2, ffn_b2, 256, out, nullptr, out);
}